// round 7
// baseline (speedup 1.0000x reference)
#include <cuda_runtime.h>
#include <cstdint>
#include <cstddef>

#define NT        32768                 // tokens = B*T
#define DM        1024
#define NE        8
#define ROWS_MAX  (2*NT + NE*128)       // 66560
#define MAX_TILES (ROWS_MAX/128)        // 520
#define STG       32768                 // per-stage: A 16KB + B 16KB
#define NSTAGE    3
#define SMEM_TOTAL (1024 + NSTAGE*STG)  // ~97 KB -> 2 CTAs/SM

// -------------------- device scratch (static, no allocs) --------------------
__device__ int      g_count[NE];
__device__ int      g_cursor[NE];
__device__ int      g_base[NE+1];
__device__ int      g_tileExpert[MAX_TILES];
__device__ int      g_rowToken[ROWS_MAX];
__device__ float    g_rowWeight[ROWS_MAX];
__device__ int      g_tokE[NT*2];
__device__ float    g_tokS[NT*2];
__device__ uint32_t g_xt[(size_t)NT * DM];         // x in tf32 bits
__device__ uint32_t g_hx[(size_t)ROWS_MAX * DM];   // h in tf32 bits
__device__ uint32_t g_w1t[(size_t)NE * DM * DM];   // w1^T tf32 [e][n][k]
__device__ uint32_t g_w2t[(size_t)NE * DM * DM];   // w2^T tf32 [e][n][k]

// -------------------- helpers ----------------------------------------------
__device__ __forceinline__ uint32_t smem_u32(const void* p) {
    uint32_t a;
    asm("{ .reg .u64 t; cvta.to.shared.u64 t, %1; cvt.u32.u64 %0, t; }" : "=r"(a) : "l"(p));
    return a;
}
__device__ __forceinline__ uint32_t f2tf(float f) {
    uint32_t r; asm("cvt.rna.tf32.f32 %0, %1;" : "=r"(r) : "f"(f)); return r;
}
__device__ __forceinline__ void cp16(uint32_t dst, const void* src, uint32_t sz) {
    asm volatile("cp.async.cg.shared.global [%0], [%1], 16, %2;"
                 :: "r"(dst), "l"(src), "r"(sz) : "memory");
}
__device__ __forceinline__ void cp_commit() { asm volatile("cp.async.commit_group;" ::: "memory"); }
__device__ __forceinline__ void cp_wait1()  { asm volatile("cp.async.wait_group 1;"  ::: "memory"); }
__device__ __forceinline__ void ldsm4(uint32_t* r, uint32_t addr) {
    asm volatile("ldmatrix.sync.aligned.m8n8.x4.shared.b16 {%0,%1,%2,%3}, [%4];"
                 : "=r"(r[0]), "=r"(r[1]), "=r"(r[2]), "=r"(r[3]) : "r"(addr));
}
__device__ __forceinline__ void mma8(float* c, const uint32_t* a, const uint32_t* b) {
    asm volatile("mma.sync.aligned.m16n8k8.row.col.f32.tf32.tf32.f32 "
                 "{%0,%1,%2,%3}, {%4,%5,%6,%7}, {%8,%9}, {%0,%1,%2,%3};"
                 : "+f"(c[0]), "+f"(c[1]), "+f"(c[2]), "+f"(c[3])
                 : "r"(a[0]), "r"(a[1]), "r"(a[2]), "r"(a[3]),
                   "r"(b[0]), "r"(b[1]));
}

// -------------------- init --------------------------------------------------
__global__ void k_init(float* __restrict__ out) {
    int i = blockIdx.x * blockDim.x + threadIdx.x;
    int nth = gridDim.x * blockDim.x;
    if (i < NE) g_count[i] = 0;
    for (int j = i; j < ROWS_MAX; j += nth) { g_rowToken[j] = -1; g_rowWeight[j] = 0.f; }
    float4 z = make_float4(0.f, 0.f, 0.f, 0.f);
    float4* o4 = (float4*)out;
    int n4 = NT * DM / 4;
    for (int j = i; j < n4; j += nth) o4[j] = z;
}

// -------------------- w[e][k][n] -> wt[e][n][k] (tf32) ----------------------
__global__ void k_transpose(const float* __restrict__ W, int which) {
    __shared__ uint32_t t[32][33];
    uint32_t* WT = which ? g_w2t : g_w1t;
    int e = blockIdx.z;
    int k0 = blockIdx.x * 32, n0 = blockIdx.y * 32;
    const float* w = W + (size_t)e * DM * DM;
    uint32_t* wt = WT + (size_t)e * DM * DM;
    for (int r = threadIdx.y; r < 32; r += 8)
        t[r][threadIdx.x] = f2tf(w[(size_t)(k0 + r) * DM + n0 + threadIdx.x]);
    __syncthreads();
    for (int r = threadIdx.y; r < 32; r += 8)
        wt[(size_t)(n0 + r) * DM + k0 + threadIdx.x] = t[threadIdx.x][r];
}

// -------------------- gating (vectorized, + fused x -> tf32) ----------------
__global__ void k_gate(const float* __restrict__ x,
                       const float* __restrict__ gw,
                       const float* __restrict__ gb) {
    int warp = (blockIdx.x * blockDim.x + threadIdx.x) >> 5;
    int lane = threadIdx.x & 31;
    if (warp >= NT) return;
    const float4* xr4 = (const float4*)(x + (size_t)warp * DM);
    uint4* xt4 = (uint4*)(g_xt + (size_t)warp * DM);
    const float4* gw4 = (const float4*)gw;
    float acc[NE];
#pragma unroll
    for (int e = 0; e < NE; e++) acc[e] = 0.f;
#pragma unroll 4
    for (int k4 = lane; k4 < DM / 4; k4 += 32) {
        float4 xv = xr4[k4];
        uint4 t;
        t.x = f2tf(xv.x); t.y = f2tf(xv.y); t.z = f2tf(xv.z); t.w = f2tf(xv.w);
        xt4[k4] = t;
#pragma unroll
        for (int j = 0; j < 4; j++) {
            float xs = (j == 0) ? xv.x : (j == 1) ? xv.y : (j == 2) ? xv.z : xv.w;
            float4 ga = gw4[k4 * 8 + j * 2];
            float4 gbv = gw4[k4 * 8 + j * 2 + 1];
            acc[0] += xs * ga.x;  acc[1] += xs * ga.y;
            acc[2] += xs * ga.z;  acc[3] += xs * ga.w;
            acc[4] += xs * gbv.x; acc[5] += xs * gbv.y;
            acc[6] += xs * gbv.z; acc[7] += xs * gbv.w;
        }
    }
#pragma unroll
    for (int e = 0; e < NE; e++)
#pragma unroll
        for (int off = 16; off; off >>= 1)
            acc[e] += __shfl_xor_sync(0xffffffffu, acc[e], off);
    if (lane == 0) {
#pragma unroll
        for (int e = 0; e < NE; e++) acc[e] += gb[e];
        int e0 = 0; float s0 = acc[0];
#pragma unroll
        for (int e = 1; e < NE; e++) if (acc[e] > s0) { s0 = acc[e]; e0 = e; }
        int e1 = -1; float s1 = -3.4e38f;
#pragma unroll
        for (int e = 0; e < NE; e++) if (e != e0 && acc[e] > s1) { s1 = acc[e]; e1 = e; }
        g_tokE[2*warp]   = e0;  g_tokS[2*warp]   = s0;
        g_tokE[2*warp+1] = e1;  g_tokS[2*warp+1] = s1;
        atomicAdd(&g_count[e0], 1);
        atomicAdd(&g_count[e1], 1);
    }
}

// -------------------- prefix (128-aligned) + tile->expert -------------------
__global__ void k_prefix() {
    if (threadIdx.x == 0) {
        int b = 0; g_base[0] = 0;
        for (int e = 0; e < NE; e++) {
            g_cursor[e] = b;
            b += ((g_count[e] + 127) >> 7) << 7;
            g_base[e+1] = b;
        }
    }
    __syncthreads();
    for (int t = threadIdx.x; t < MAX_TILES; t += blockDim.x) {
        int r = t << 7;
        int e = -1;
        for (int q = 0; q < NE; q++)
            if (r >= g_base[q] && r < g_base[q+1]) e = q;
        g_tileExpert[t] = e;
    }
}

__global__ void k_scatter() {
    int i = blockIdx.x * blockDim.x + threadIdx.x;
    if (i >= NT * 2) return;
    int e = g_tokE[i];
    int p = atomicAdd(&g_cursor[e], 1);
    g_rowToken[p]  = i >> 1;
    g_rowWeight[p] = g_tokS[i];
}

// -------------------- pipelined tf32 grouped GEMM ---------------------------
// CTA 128x128, 128 threads (4 warps 2x2, warp tile 64x64), BK=32, 3-stage
// cp.async, ldmatrix fragment loads (double-buffered across k8), 2 CTAs/SM.
template<int PHASE>
__global__ void __launch_bounds__(128, 2)
k_gemm(const float* __restrict__ Bias, float* __restrict__ Out) {
    extern __shared__ char smem[];
    int e = g_tileExpert[blockIdx.y];
    if (e < 0) return;
    const int rowBase = blockIdx.y * 128, colBase = blockIdx.x * 128;
    const int tid = threadIdx.x, lane = tid & 31, wid = tid >> 5;

    float* sBias = (float*)smem;
    sBias[tid] = Bias[e * DM + colBase + tid];

    const uint32_t sb = smem_u32(smem) + 1024;

    // ---- producer: 8 A-chunks + 8 B-chunks (16B) per thread per stage ----
    const int tr = tid >> 3, ch = tid & 7;                 // tr 0..15, ch 0..7
    const uint32_t dOff0 = tr * 128 + ((ch * 16) ^ ((tr & 7) << 4));
    const char* wT = (const char*)((PHASE == 1 ? g_w1t : g_w2t) + ((size_t)e << 20));
    const char* aBase = (PHASE == 1) ? (const char*)g_xt
                                     : (const char*)(g_hx + (size_t)rowBase * DM);
    uint32_t aOff[8], aSz[8], bOff[8];
#pragma unroll
    for (int i = 0; i < 8; i++) {
        int row = tr + 16 * i;
        if (PHASE == 1) {
            int tok = g_rowToken[rowBase + row];
            aOff[i] = (uint32_t)(tok < 0 ? 0 : tok) * 4096u + ch * 16;
            aSz[i]  = (tok < 0) ? 0u : 16u;
        } else {
            aOff[i] = (uint32_t)row * 4096u + ch * 16;
            aSz[i]  = 16u;
        }
        bOff[i] = (uint32_t)(colBase + row) * 4096u + ch * 16;
    }

#define PRODUCE(STAGE, KB)                                                      \
    {                                                                           \
        uint32_t base_ = sb + (STAGE) * STG;                                    \
        _Pragma("unroll")                                                       \
        for (int i_ = 0; i_ < 8; i_++) {                                        \
            cp16(base_ + dOff0 + i_ * 2048,         aBase + aOff[i_] + (KB), aSz[i_]); \
            cp16(base_ + 16384 + dOff0 + i_ * 2048, wT + bOff[i_] + (KB), 16); \
        }                                                                       \
    }

    PRODUCE(0, 0);    cp_commit();
    PRODUCE(1, 128);  cp_commit();

    // ---- consumer: ldmatrix addressing ----
    const int g = lane >> 2, tig = lane & 3;
    const int warpM = wid >> 1, warpN = wid & 1;
    const int lm = lane >> 3, lj = lane & 7;       // matrix idx, row within matrix
    const uint32_t swzMask = (uint32_t)lj << 4;
    const uint32_t aHalf = (uint32_t)(lm >> 1) << 4;   // A: m0,m1 half0; m2,m3 half1
    const uint32_t bHalf = (uint32_t)(lm & 1) << 4;    // B: m0,m2 half0; m1,m3 half1
    uint32_t aRow[4], bRow[4];
#pragma unroll
    for (int ma = 0; ma < 4; ma++)
        aRow[ma] = (uint32_t)(warpM * 64 + ma * 16 + (lm & 1) * 8 + lj) * 128;
#pragma unroll
    for (int p = 0; p < 4; p++)
        bRow[p] = 16384u + (uint32_t)(warpN * 64 + p * 16 + (lm >> 1) * 8 + lj) * 128;

    float c[4][8][4];
#pragma unroll
    for (int i = 0; i < 4; i++)
#pragma unroll
        for (int j = 0; j < 8; j++)
#pragma unroll
            for (int q = 0; q < 4; q++) c[i][j][q] = 0.f;

    uint32_t a[2][4][4], b[2][4][4];

#define LDFRAGS(K8, BUF, STGA)                                                  \
    {                                                                           \
        const uint32_t kterm_ = (uint32_t)(K8) * 32;                            \
        _Pragma("unroll")                                                       \
        for (int ma_ = 0; ma_ < 4; ma_++)                                       \
            ldsm4(a[BUF][ma_], (STGA) + aRow[ma_] + ((kterm_ + aHalf) ^ swzMask)); \
        _Pragma("unroll")                                                       \
        for (int p_ = 0; p_ < 4; p_++)                                          \
            ldsm4(b[BUF][p_], (STGA) + bRow[p_] + ((kterm_ + bHalf) ^ swzMask)); \
    }

    for (int kk = 0; kk < 32; kk++) {
        cp_wait1();
        __syncthreads();
        if (kk + 2 < 32) {
            int s = (kk + 2) % NSTAGE;
            int kB = (kk + 2) * 128;
            PRODUCE(s, kB);
        }
        cp_commit();   // empty group in tail keeps wait_group<1> counting uniform

        const uint32_t stgA = sb + (kk % NSTAGE) * STG;
        LDFRAGS(0, 0, stgA);
#pragma unroll
        for (int k8 = 0; k8 < 4; k8++) {
            if (k8 < 3) LDFRAGS(k8 + 1, (k8 + 1) & 1, stgA);
            const int cur = k8 & 1;
#pragma unroll
            for (int ma = 0; ma < 4; ma++)
#pragma unroll
                for (int nb = 0; nb < 8; nb++)
                    mma8(c[ma][nb], a[cur][ma], &b[cur][nb >> 1][(nb & 1) * 2]);
        }
    }
#undef LDFRAGS
#undef PRODUCE

    // ---- epilogue ----
#pragma unroll
    for (int ma = 0; ma < 4; ma++) {
#pragma unroll
        for (int half = 0; half < 2; half++) {
            int grow = rowBase + warpM * 64 + ma * 16 + g + half * 8;
            if (PHASE == 1) {
                uint32_t* hrow = g_hx + (size_t)grow * DM + colBase;
#pragma unroll
                for (int nb = 0; nb < 8; nb++) {
                    int cn = warpN * 64 + nb * 8 + tig * 2;
                    float v0 = c[ma][nb][half*2+0] + sBias[cn];
                    float v1 = c[ma][nb][half*2+1] + sBias[cn+1];
                    v0 = fmaxf(v0, 0.f); v1 = fmaxf(v1, 0.f);
                    uint2 u; u.x = f2tf(v0); u.y = f2tf(v1);
                    *(uint2*)(hrow + cn) = u;
                }
            } else {
                int tok = g_rowToken[grow];
                if (tok >= 0) {
                    float w = g_rowWeight[grow];
                    float* orow = Out + (size_t)tok * DM + colBase;
#pragma unroll
                    for (int nb = 0; nb < 8; nb++) {
                        int cn = warpN * 64 + nb * 8 + tig * 2;
                        float v0 = (c[ma][nb][half*2+0] + sBias[cn])   * w;
                        float v1 = (c[ma][nb][half*2+1] + sBias[cn+1]) * w;
                        asm volatile("red.global.add.v2.f32 [%0], {%1,%2};"
                                     :: "l"(orow + cn), "f"(v0), "f"(v1) : "memory");
                    }
                }
            }
        }
    }
}

// -------------------- launch -----------------------------------------------
extern "C" void kernel_launch(void* const* d_in, const int* in_sizes, int n_in,
                              void* d_out, int out_size) {
    const float* x  = (const float*)d_in[0];
    const float* gw = (const float*)d_in[1];
    const float* gb = (const float*)d_in[2];
    const float* w1 = (const float*)d_in[3];
    const float* b1 = (const float*)d_in[4];
    const float* w2 = (const float*)d_in[5];
    const float* b2 = (const float*)d_in[6];
    float* out = (float*)d_out;

    static int smemSet = 0;
    if (!smemSet) {
        cudaFuncSetAttribute(k_gemm<1>, cudaFuncAttributeMaxDynamicSharedMemorySize, SMEM_TOTAL);
        cudaFuncSetAttribute(k_gemm<2>, cudaFuncAttributeMaxDynamicSharedMemorySize, SMEM_TOTAL);
        smemSet = 1;
    }

    k_init<<<512, 256>>>(out);
    k_transpose<<<dim3(32, 32, NE), dim3(32, 8)>>>(w1, 0);
    k_transpose<<<dim3(32, 32, NE), dim3(32, 8)>>>(w2, 1);
    k_gate<<<NT / 8, 256>>>(x, gw, gb);
    k_prefix<<<1, 128>>>();
    k_scatter<<<NT * 2 / 256, 256>>>();
    dim3 gg(DM / 128, MAX_TILES);
    k_gemm<1><<<gg, 128, SMEM_TOTAL>>>(b1, nullptr);
    k_gemm<2><<<gg, 128, SMEM_TOTAL>>>(b2, out);
}

// round 8
// speedup vs baseline: 1.6388x; 1.6388x over previous
#include <cuda_runtime.h>
#include <cstdint>
#include <cstddef>

#define NT        32768                 // tokens = B*T
#define DM        1024
#define NE        8
#define ROWS_MAX  (2*NT + NE*128)       // 66560
#define MAX_TILES (ROWS_MAX/128)        // 520
#define STG       32768                 // per-stage: A 16KB + B 16KB
#define NSTAGE    3
#define SMEM_TOTAL (1024 + NSTAGE*STG)  // ~97 KB -> 2 CTAs/SM

// -------------------- device scratch (static, no allocs) --------------------
__device__ int      g_count[NE];
__device__ int      g_cursor[NE];
__device__ int      g_base[NE+1];
__device__ int      g_tileExpert[MAX_TILES];
__device__ int      g_rowToken[ROWS_MAX];
__device__ float    g_rowWeight[ROWS_MAX];
__device__ int      g_tokE[NT*2];
__device__ float    g_tokS[NT*2];
__device__ uint32_t g_xt[(size_t)NT * DM];         // x in tf32 bits
__device__ uint32_t g_hx[(size_t)ROWS_MAX * DM];   // h in tf32 bits
__device__ uint32_t g_w1t[(size_t)NE * DM * DM];   // w1^T tf32 [e][n][k]
__device__ uint32_t g_w2t[(size_t)NE * DM * DM];   // w2^T tf32 [e][n][k]

// -------------------- helpers ----------------------------------------------
__device__ __forceinline__ uint32_t smem_u32(const void* p) {
    uint32_t a;
    asm("{ .reg .u64 t; cvta.to.shared.u64 t, %1; cvt.u32.u64 %0, t; }" : "=r"(a) : "l"(p));
    return a;
}
__device__ __forceinline__ uint32_t f2tf(float f) {
    uint32_t r; asm("cvt.rna.tf32.f32 %0, %1;" : "=r"(r) : "f"(f)); return r;
}
__device__ __forceinline__ void cp16(uint32_t dst, const void* src, uint32_t sz) {
    asm volatile("cp.async.cg.shared.global [%0], [%1], 16, %2;"
                 :: "r"(dst), "l"(src), "r"(sz) : "memory");
}
__device__ __forceinline__ void cp_commit() { asm volatile("cp.async.commit_group;" ::: "memory"); }
__device__ __forceinline__ void cp_wait1()  { asm volatile("cp.async.wait_group 1;"  ::: "memory"); }
__device__ __forceinline__ void ldsm4(uint32_t* r, uint32_t addr) {
    asm volatile("ldmatrix.sync.aligned.m8n8.x4.shared.b16 {%0,%1,%2,%3}, [%4];"
                 : "=r"(r[0]), "=r"(r[1]), "=r"(r[2]), "=r"(r[3]) : "r"(addr));
}
__device__ __forceinline__ void mma8(float* c, const uint32_t* a, const uint32_t* b) {
    asm volatile("mma.sync.aligned.m16n8k8.row.col.f32.tf32.tf32.f32 "
                 "{%0,%1,%2,%3}, {%4,%5,%6,%7}, {%8,%9}, {%0,%1,%2,%3};"
                 : "+f"(c[0]), "+f"(c[1]), "+f"(c[2]), "+f"(c[3])
                 : "r"(a[0]), "r"(a[1]), "r"(a[2]), "r"(a[3]),
                   "r"(b[0]), "r"(b[1]));
}

// -------------------- init --------------------------------------------------
__global__ void k_init(float* __restrict__ out) {
    int i = blockIdx.x * blockDim.x + threadIdx.x;
    int nth = gridDim.x * blockDim.x;
    if (i < NE) g_count[i] = 0;
    for (int j = i; j < ROWS_MAX; j += nth) { g_rowToken[j] = -1; g_rowWeight[j] = 0.f; }
    float4 z = make_float4(0.f, 0.f, 0.f, 0.f);
    float4* o4 = (float4*)out;
    int n4 = NT * DM / 4;
    for (int j = i; j < n4; j += nth) o4[j] = z;
}

// -------------------- w[e][k][n] -> wt[e][n][k] (tf32) ----------------------
__global__ void k_transpose(const float* __restrict__ W, int which) {
    __shared__ uint32_t t[32][33];
    uint32_t* WT = which ? g_w2t : g_w1t;
    int e = blockIdx.z;
    int k0 = blockIdx.x * 32, n0 = blockIdx.y * 32;
    const float* w = W + (size_t)e * DM * DM;
    uint32_t* wt = WT + (size_t)e * DM * DM;
    for (int r = threadIdx.y; r < 32; r += 8)
        t[r][threadIdx.x] = f2tf(w[(size_t)(k0 + r) * DM + n0 + threadIdx.x]);
    __syncthreads();
    for (int r = threadIdx.y; r < 32; r += 8)
        wt[(size_t)(n0 + r) * DM + k0 + threadIdx.x] = t[threadIdx.x][r];
}

// -------------------- gating: gw staged transposed in smem ------------------
// CTA = 8 warps x 8 tokens each; sgw[e][k] so per-e rows give lane-consecutive
// conflict-free float4 LDS. Fused x -> tf32 conversion.
#define GTOK 8
__global__ void __launch_bounds__(256)
k_gate(const float* __restrict__ x,
       const float* __restrict__ gw,
       const float* __restrict__ gb) {
    __shared__ float sgw[NE * DM];
    int tid = threadIdx.x;
    // load + transpose gw [k][e] -> sgw [e][k]
    for (int i = tid; i < DM * NE / 4; i += 256) {
        float4 v = ((const float4*)gw)[i];
        int k = i >> 1, e0 = (i & 1) * 4;
        sgw[(e0+0) * DM + k] = v.x;
        sgw[(e0+1) * DM + k] = v.y;
        sgw[(e0+2) * DM + k] = v.z;
        sgw[(e0+3) * DM + k] = v.w;
    }
    __syncthreads();

    int warp = tid >> 5, lane = tid & 31;
    int tokBase = (blockIdx.x * 8 + warp) * GTOK;
    for (int t = 0; t < GTOK; t++) {
        int tok = tokBase + t;
        const float4* xr4 = (const float4*)(x + (size_t)tok * DM);
        uint4* xt4 = (uint4*)(g_xt + (size_t)tok * DM);
        float acc[NE];
#pragma unroll
        for (int e = 0; e < NE; e++) acc[e] = 0.f;
#pragma unroll
        for (int k4 = lane; k4 < DM / 4; k4 += 32) {
            float4 xv = xr4[k4];
            uint4 u;
            u.x = f2tf(xv.x); u.y = f2tf(xv.y); u.z = f2tf(xv.z); u.w = f2tf(xv.w);
            xt4[k4] = u;
#pragma unroll
            for (int e = 0; e < NE; e++) {
                float4 g4 = ((const float4*)(sgw + e * DM))[k4];
                acc[e] += xv.x * g4.x + xv.y * g4.y + xv.z * g4.z + xv.w * g4.w;
            }
        }
#pragma unroll
        for (int e = 0; e < NE; e++)
#pragma unroll
            for (int off = 16; off; off >>= 1)
                acc[e] += __shfl_xor_sync(0xffffffffu, acc[e], off);
        if (lane == 0) {
#pragma unroll
            for (int e = 0; e < NE; e++) acc[e] += gb[e];
            int e0 = 0; float s0 = acc[0];
#pragma unroll
            for (int e = 1; e < NE; e++) if (acc[e] > s0) { s0 = acc[e]; e0 = e; }
            int e1 = -1; float s1 = -3.4e38f;
#pragma unroll
            for (int e = 0; e < NE; e++) if (e != e0 && acc[e] > s1) { s1 = acc[e]; e1 = e; }
            g_tokE[2*tok]   = e0;  g_tokS[2*tok]   = s0;
            g_tokE[2*tok+1] = e1;  g_tokS[2*tok+1] = s1;
            atomicAdd(&g_count[e0], 1);
            atomicAdd(&g_count[e1], 1);
        }
    }
}

// -------------------- prefix (128-aligned) + tile->expert -------------------
__global__ void k_prefix() {
    if (threadIdx.x == 0) {
        int b = 0; g_base[0] = 0;
        for (int e = 0; e < NE; e++) {
            g_cursor[e] = b;
            b += ((g_count[e] + 127) >> 7) << 7;
            g_base[e+1] = b;
        }
    }
    __syncthreads();
    for (int t = threadIdx.x; t < MAX_TILES; t += blockDim.x) {
        int r = t << 7;
        int e = -1;
        for (int q = 0; q < NE; q++)
            if (r >= g_base[q] && r < g_base[q+1]) e = q;
        g_tileExpert[t] = e;
    }
}

__global__ void k_scatter() {
    int i = blockIdx.x * blockDim.x + threadIdx.x;
    if (i >= NT * 2) return;
    int e = g_tokE[i];
    int p = atomicAdd(&g_cursor[e], 1);
    g_rowToken[p]  = i >> 1;
    g_rowWeight[p] = g_tokS[i];
}

// -------------------- pipelined tf32 grouped GEMM (round-6 winner) ----------
// CTA 128x128, 128 threads (4 warps 2x2, warp tile 64x64), BK=32, 3-stage
// cp.async, single-buffered ldmatrix fragment loads, 2 CTAs/SM.
template<int PHASE>
__global__ void __launch_bounds__(128, 2)
k_gemm(const float* __restrict__ Bias, float* __restrict__ Out) {
    extern __shared__ char smem[];
    int e = g_tileExpert[blockIdx.y];
    if (e < 0) return;
    const int rowBase = blockIdx.y * 128, colBase = blockIdx.x * 128;
    const int tid = threadIdx.x, lane = tid & 31, wid = tid >> 5;

    float* sBias = (float*)smem;
    sBias[tid] = Bias[e * DM + colBase + tid];

    const uint32_t sb = smem_u32(smem) + 1024;

    // ---- producer: 8 A-chunks + 8 B-chunks (16B) per thread per stage ----
    const int tr = tid >> 3, ch = tid & 7;                 // tr 0..15, ch 0..7
    const uint32_t dOff0 = tr * 128 + ((ch * 16) ^ ((tr & 7) << 4));
    const char* wT = (const char*)((PHASE == 1 ? g_w1t : g_w2t) + ((size_t)e << 20));
    const char* aBase = (PHASE == 1) ? (const char*)g_xt
                                     : (const char*)(g_hx + (size_t)rowBase * DM);
    uint32_t aOff[8], aSz[8], bOff[8];
#pragma unroll
    for (int i = 0; i < 8; i++) {
        int row = tr + 16 * i;
        if (PHASE == 1) {
            int tok = g_rowToken[rowBase + row];
            aOff[i] = (uint32_t)(tok < 0 ? 0 : tok) * 4096u + ch * 16;
            aSz[i]  = (tok < 0) ? 0u : 16u;
        } else {
            aOff[i] = (uint32_t)row * 4096u + ch * 16;
            aSz[i]  = 16u;
        }
        bOff[i] = (uint32_t)(colBase + row) * 4096u + ch * 16;
    }

#define PRODUCE(STAGE, KB)                                                      \
    {                                                                           \
        uint32_t base_ = sb + (STAGE) * STG;                                    \
        _Pragma("unroll")                                                       \
        for (int i_ = 0; i_ < 8; i_++) {                                        \
            cp16(base_ + dOff0 + i_ * 2048,         aBase + aOff[i_] + (KB), aSz[i_]); \
            cp16(base_ + 16384 + dOff0 + i_ * 2048, wT + bOff[i_] + (KB), 16); \
        }                                                                       \
    }

    PRODUCE(0, 0);    cp_commit();
    PRODUCE(1, 128);  cp_commit();

    // ---- consumer: ldmatrix addressing ----
    const int g = lane >> 2, tig = lane & 3;
    const int warpM = wid >> 1, warpN = wid & 1;
    const int lm = lane >> 3, lj = lane & 7;       // matrix idx, row within matrix
    const uint32_t swzMask = (uint32_t)lj << 4;
    const uint32_t aHalf = (uint32_t)(lm >> 1) << 4;   // A: m0,m1 half0; m2,m3 half1
    const uint32_t bHalf = (uint32_t)(lm & 1) << 4;    // B: m0,m2 half0; m1,m3 half1
    uint32_t aRow[4], bRow[4];
#pragma unroll
    for (int ma = 0; ma < 4; ma++)
        aRow[ma] = (uint32_t)(warpM * 64 + ma * 16 + (lm & 1) * 8 + lj) * 128;
#pragma unroll
    for (int p = 0; p < 4; p++)
        bRow[p] = 16384u + (uint32_t)(warpN * 64 + p * 16 + (lm >> 1) * 8 + lj) * 128;

    float c[4][8][4];
#pragma unroll
    for (int i = 0; i < 4; i++)
#pragma unroll
        for (int j = 0; j < 8; j++)
#pragma unroll
            for (int q = 0; q < 4; q++) c[i][j][q] = 0.f;

    for (int kk = 0; kk < 32; kk++) {
        cp_wait1();
        __syncthreads();
        if (kk + 2 < 32) {
            int s = (kk + 2) % NSTAGE;
            int kB = (kk + 2) * 128;
            PRODUCE(s, kB);
        }
        cp_commit();   // empty group in tail keeps wait_group<1> counting uniform

        const uint32_t stgA = sb + (kk % NSTAGE) * STG;
#pragma unroll
        for (int k8 = 0; k8 < 4; k8++) {
            const uint32_t kterm = (uint32_t)k8 * 32;
            uint32_t a[4][4], b[4][4];
#pragma unroll
            for (int ma = 0; ma < 4; ma++)
                ldsm4(a[ma], stgA + aRow[ma] + ((kterm + aHalf) ^ swzMask));
#pragma unroll
            for (int p = 0; p < 4; p++)
                ldsm4(b[p], stgA + bRow[p] + ((kterm + bHalf) ^ swzMask));
#pragma unroll
            for (int ma = 0; ma < 4; ma++)
#pragma unroll
                for (int nb = 0; nb < 8; nb++)
                    mma8(c[ma][nb], a[ma], &b[nb >> 1][(nb & 1) * 2]);
        }
    }
#undef PRODUCE

    // ---- epilogue ----
#pragma unroll
    for (int ma = 0; ma < 4; ma++) {
#pragma unroll
        for (int half = 0; half < 2; half++) {
            int grow = rowBase + warpM * 64 + ma * 16 + g + half * 8;
            if (PHASE == 1) {
                uint32_t* hrow = g_hx + (size_t)grow * DM + colBase;
#pragma unroll
                for (int nb = 0; nb < 8; nb++) {
                    int cn = warpN * 64 + nb * 8 + tig * 2;
                    float v0 = c[ma][nb][half*2+0] + sBias[cn];
                    float v1 = c[ma][nb][half*2+1] + sBias[cn+1];
                    v0 = fmaxf(v0, 0.f); v1 = fmaxf(v1, 0.f);
                    uint2 u; u.x = f2tf(v0); u.y = f2tf(v1);
                    *(uint2*)(hrow + cn) = u;
                }
            } else {
                int tok = g_rowToken[grow];
                if (tok >= 0) {
                    float w = g_rowWeight[grow];
                    float* orow = Out + (size_t)tok * DM + colBase;
#pragma unroll
                    for (int nb = 0; nb < 8; nb++) {
                        int cn = warpN * 64 + nb * 8 + tig * 2;
                        float v0 = (c[ma][nb][half*2+0] + sBias[cn])   * w;
                        float v1 = (c[ma][nb][half*2+1] + sBias[cn+1]) * w;
                        asm volatile("red.global.add.v2.f32 [%0], {%1,%2};"
                                     :: "l"(orow + cn), "f"(v0), "f"(v1) : "memory");
                    }
                }
            }
        }
    }
}

// -------------------- launch -----------------------------------------------
extern "C" void kernel_launch(void* const* d_in, const int* in_sizes, int n_in,
                              void* d_out, int out_size) {
    const float* x  = (const float*)d_in[0];
    const float* gw = (const float*)d_in[1];
    const float* gb = (const float*)d_in[2];
    const float* w1 = (const float*)d_in[3];
    const float* b1 = (const float*)d_in[4];
    const float* w2 = (const float*)d_in[5];
    const float* b2 = (const float*)d_in[6];
    float* out = (float*)d_out;

    static int smemSet = 0;
    if (!smemSet) {
        cudaFuncSetAttribute(k_gemm<1>, cudaFuncAttributeMaxDynamicSharedMemorySize, SMEM_TOTAL);
        cudaFuncSetAttribute(k_gemm<2>, cudaFuncAttributeMaxDynamicSharedMemorySize, SMEM_TOTAL);
        smemSet = 1;
    }

    k_init<<<512, 256>>>(out);
    k_transpose<<<dim3(32, 32, NE), dim3(32, 8)>>>(w1, 0);
    k_transpose<<<dim3(32, 32, NE), dim3(32, 8)>>>(w2, 1);
    k_gate<<<NT / 64, 256>>>(x, gw, gb);
    k_prefix<<<1, 128>>>();
    k_scatter<<<NT * 2 / 256, 256>>>();
    dim3 gg(DM / 128, MAX_TILES);
    k_gemm<1><<<gg, 128, SMEM_TOTAL>>>(b1, nullptr);
    k_gemm<2><<<gg, 128, SMEM_TOTAL>>>(b2, out);
}

// round 9
// speedup vs baseline: 2.9191x; 1.7813x over previous
#include <cuda_runtime.h>
#include <cuda_fp16.h>
#include <cstdint>
#include <cstddef>

#define NT        32768                 // tokens = B*T
#define DM        1024
#define NE        8
#define ROWS_MAX  (2*NT + NE*128)       // 66560
#define MAX_TILES (ROWS_MAX/128)        // 520
#define STG       32768                 // per-stage: A 16KB + B 16KB (fp16, BK=64)
#define NSTAGE    3
#define SMEM_TOTAL (1024 + NSTAGE*STG)  // ~97 KB -> 2 CTAs/SM

// -------------------- device scratch (static, no allocs) --------------------
__device__ int      g_count[NE];
__device__ int      g_cursor[NE];
__device__ int      g_base[NE+1];
__device__ int      g_tileExpert[MAX_TILES];
__device__ int      g_rowToken[ROWS_MAX];
__device__ float    g_rowWeight[ROWS_MAX];
__device__ int      g_tokE[NT*2];
__device__ float    g_tokS[NT*2];
__device__ __half   g_xh[(size_t)NT * DM];         // x in fp16
__device__ __half   g_hh[(size_t)ROWS_MAX * DM];   // h in fp16
__device__ __half   g_w1t[(size_t)NE * DM * DM];   // w1^T fp16 [e][n][k]
__device__ __half   g_w2t[(size_t)NE * DM * DM];   // w2^T fp16 [e][n][k]

// -------------------- helpers ----------------------------------------------
__device__ __forceinline__ uint32_t smem_u32(const void* p) {
    uint32_t a;
    asm("{ .reg .u64 t; cvta.to.shared.u64 t, %1; cvt.u32.u64 %0, t; }" : "=r"(a) : "l"(p));
    return a;
}
__device__ __forceinline__ uint32_t f2h2(float lo, float hi) {
    uint32_t r;
    asm("cvt.rn.f16x2.f32 %0, %1, %2;" : "=r"(r) : "f"(hi), "f"(lo));
    return r;
}
__device__ __forceinline__ void cp16(uint32_t dst, const void* src, uint32_t sz) {
    asm volatile("cp.async.cg.shared.global [%0], [%1], 16, %2;"
                 :: "r"(dst), "l"(src), "r"(sz) : "memory");
}
__device__ __forceinline__ void cp_commit() { asm volatile("cp.async.commit_group;" ::: "memory"); }
__device__ __forceinline__ void cp_wait1()  { asm volatile("cp.async.wait_group 1;"  ::: "memory"); }
__device__ __forceinline__ void ldsm4(uint32_t* r, uint32_t addr) {
    asm volatile("ldmatrix.sync.aligned.m8n8.x4.shared.b16 {%0,%1,%2,%3}, [%4];"
                 : "=r"(r[0]), "=r"(r[1]), "=r"(r[2]), "=r"(r[3]) : "r"(addr));
}
__device__ __forceinline__ void mma16(float* c, const uint32_t* a, uint32_t b0, uint32_t b1) {
    asm volatile("mma.sync.aligned.m16n8k16.row.col.f32.f16.f16.f32 "
                 "{%0,%1,%2,%3}, {%4,%5,%6,%7}, {%8,%9}, {%0,%1,%2,%3};"
                 : "+f"(c[0]), "+f"(c[1]), "+f"(c[2]), "+f"(c[3])
                 : "r"(a[0]), "r"(a[1]), "r"(a[2]), "r"(a[3]),
                   "r"(b0), "r"(b1));
}

// -------------------- init --------------------------------------------------
__global__ void k_init(float* __restrict__ out) {
    int i = blockIdx.x * blockDim.x + threadIdx.x;
    int nth = gridDim.x * blockDim.x;
    if (i < NE) g_count[i] = 0;
    for (int j = i; j < ROWS_MAX; j += nth) { g_rowToken[j] = -1; g_rowWeight[j] = 0.f; }
    float4 z = make_float4(0.f, 0.f, 0.f, 0.f);
    float4* o4 = (float4*)out;
    int n4 = NT * DM / 4;
    for (int j = i; j < n4; j += nth) o4[j] = z;
}

// -------------------- w[e][k][n] -> wt[e][n][k] (fp16) ----------------------
__global__ void k_transpose(const float* __restrict__ W, int which) {
    __shared__ __half t[32][34];
    __half* WT = which ? g_w2t : g_w1t;
    int e = blockIdx.z;
    int k0 = blockIdx.x * 32, n0 = blockIdx.y * 32;
    const float* w = W + (size_t)e * DM * DM;
    __half* wt = WT + (size_t)e * DM * DM;
    for (int r = threadIdx.y; r < 32; r += 8)
        t[r][threadIdx.x] = __float2half_rn(w[(size_t)(k0 + r) * DM + n0 + threadIdx.x]);
    __syncthreads();
    for (int r = threadIdx.y; r < 32; r += 8)
        wt[(size_t)(n0 + r) * DM + k0 + threadIdx.x] = t[threadIdx.x][r];
}

// -------------------- gating: gw staged transposed in smem ------------------
#define GTOK 8
__global__ void __launch_bounds__(256)
k_gate(const float* __restrict__ x,
       const float* __restrict__ gw,
       const float* __restrict__ gb) {
    __shared__ float sgw[NE * DM];
    int tid = threadIdx.x;
    for (int i = tid; i < DM * NE / 4; i += 256) {
        float4 v = ((const float4*)gw)[i];
        int k = i >> 1, e0 = (i & 1) * 4;
        sgw[(e0+0) * DM + k] = v.x;
        sgw[(e0+1) * DM + k] = v.y;
        sgw[(e0+2) * DM + k] = v.z;
        sgw[(e0+3) * DM + k] = v.w;
    }
    __syncthreads();

    int warp = tid >> 5, lane = tid & 31;
    int tokBase = (blockIdx.x * 8 + warp) * GTOK;
#pragma unroll 1
    for (int t = 0; t < GTOK; t++) {
        int tok = tokBase + t;
        const float4* xr4 = (const float4*)(x + (size_t)tok * DM);
        uint2* xh2 = (uint2*)(g_xh + (size_t)tok * DM);
        float acc[NE];
#pragma unroll
        for (int e = 0; e < NE; e++) acc[e] = 0.f;
#pragma unroll 2
        for (int k4 = lane; k4 < DM / 4; k4 += 32) {
            float4 xv = xr4[k4];
            uint2 u;
            u.x = f2h2(xv.x, xv.y);
            u.y = f2h2(xv.z, xv.w);
            xh2[k4] = u;
#pragma unroll
            for (int e = 0; e < NE; e++) {
                float4 g4 = ((const float4*)(sgw + e * DM))[k4];
                acc[e] += xv.x * g4.x + xv.y * g4.y + xv.z * g4.z + xv.w * g4.w;
            }
        }
#pragma unroll
        for (int e = 0; e < NE; e++)
#pragma unroll
            for (int off = 16; off; off >>= 1)
                acc[e] += __shfl_xor_sync(0xffffffffu, acc[e], off);
        if (lane == 0) {
#pragma unroll
            for (int e = 0; e < NE; e++) acc[e] += gb[e];
            int e0 = 0; float s0 = acc[0];
#pragma unroll
            for (int e = 1; e < NE; e++) if (acc[e] > s0) { s0 = acc[e]; e0 = e; }
            int e1 = -1; float s1 = -3.4e38f;
#pragma unroll
            for (int e = 0; e < NE; e++) if (e != e0 && acc[e] > s1) { s1 = acc[e]; e1 = e; }
            g_tokE[2*tok]   = e0;  g_tokS[2*tok]   = s0;
            g_tokE[2*tok+1] = e1;  g_tokS[2*tok+1] = s1;
            atomicAdd(&g_count[e0], 1);
            atomicAdd(&g_count[e1], 1);
        }
    }
}

// -------------------- prefix (128-aligned) + tile->expert -------------------
__global__ void k_prefix() {
    if (threadIdx.x == 0) {
        int b = 0; g_base[0] = 0;
        for (int e = 0; e < NE; e++) {
            g_cursor[e] = b;
            b += ((g_count[e] + 127) >> 7) << 7;
            g_base[e+1] = b;
        }
    }
    __syncthreads();
    for (int t = threadIdx.x; t < MAX_TILES; t += blockDim.x) {
        int r = t << 7;
        int e = -1;
        for (int q = 0; q < NE; q++)
            if (r >= g_base[q] && r < g_base[q+1]) e = q;
        g_tileExpert[t] = e;
    }
}

__global__ void k_scatter() {
    int i = blockIdx.x * blockDim.x + threadIdx.x;
    if (i >= NT * 2) return;
    int e = g_tokE[i];
    int p = atomicAdd(&g_cursor[e], 1);
    g_rowToken[p]  = i >> 1;
    g_rowWeight[p] = g_tokS[i];
}

// -------------------- pipelined fp16 grouped GEMM ---------------------------
// CTA 128x128, 128 threads (4 warps 2x2, warp tile 64x64), BK=64 (128B rows),
// 3-stage cp.async, ldmatrix fragments, m16n8k16 f16 mma, 2 CTAs/SM.
template<int PHASE>
__global__ void __launch_bounds__(128, 2)
k_gemm(const float* __restrict__ Bias, float* __restrict__ Out) {
    extern __shared__ char smem[];
    int e = g_tileExpert[blockIdx.y];
    if (e < 0) return;
    const int rowBase = blockIdx.y * 128, colBase = blockIdx.x * 128;
    const int tid = threadIdx.x, lane = tid & 31, wid = tid >> 5;

    float* sBias = (float*)smem;
    sBias[tid] = Bias[e * DM + colBase + tid];

    const uint32_t sb = smem_u32(smem) + 1024;

    // ---- producer: 8 A-chunks + 8 B-chunks (16B) per thread per stage ----
    const int tr = tid >> 3, ch = tid & 7;                 // tr 0..15, ch 0..7
    const uint32_t dOff0 = tr * 128 + ((ch * 16) ^ ((tr & 7) << 4));
    const char* wT = (const char*)((PHASE == 1 ? g_w1t : g_w2t) + ((size_t)e << 20));
    const char* aBase = (PHASE == 1) ? (const char*)g_xh
                                     : (const char*)(g_hh + (size_t)rowBase * DM);
    uint32_t aOff[8], aSz[8], bOff[8];
#pragma unroll
    for (int i = 0; i < 8; i++) {
        int row = tr + 16 * i;
        if (PHASE == 1) {
            int tok = g_rowToken[rowBase + row];
            aOff[i] = (uint32_t)(tok < 0 ? 0 : tok) * 2048u + ch * 16;
            aSz[i]  = (tok < 0) ? 0u : 16u;
        } else {
            aOff[i] = (uint32_t)row * 2048u + ch * 16;
            aSz[i]  = 16u;
        }
        bOff[i] = (uint32_t)(colBase + row) * 2048u + ch * 16;
    }

#define PRODUCE(STAGE, KB)                                                      \
    {                                                                           \
        uint32_t base_ = sb + (STAGE) * STG;                                    \
        _Pragma("unroll")                                                       \
        for (int i_ = 0; i_ < 8; i_++) {                                        \
            cp16(base_ + dOff0 + i_ * 2048,         aBase + aOff[i_] + (KB), aSz[i_]); \
            cp16(base_ + 16384 + dOff0 + i_ * 2048, wT + bOff[i_] + (KB), 16); \
        }                                                                       \
    }

    PRODUCE(0, 0);    cp_commit();
    PRODUCE(1, 128);  cp_commit();

    // ---- consumer: ldmatrix addressing ----
    const int g = lane >> 2, tig = lane & 3;
    const int warpM = wid >> 1, warpN = wid & 1;
    const int lm = lane >> 3, lj = lane & 7;       // matrix idx, row within matrix
    const uint32_t swzMask = (uint32_t)lj << 4;
    const uint32_t aHalf = (uint32_t)(lm >> 1) << 4;   // A: m0,m1 khalf0; m2,m3 khalf1
    const uint32_t bHalf = (uint32_t)(lm & 1) << 4;    // B: m0,m2 khalf0; m1,m3 khalf1
    uint32_t aRow[4], bRow[4];
#pragma unroll
    for (int ma = 0; ma < 4; ma++)
        aRow[ma] = (uint32_t)(warpM * 64 + ma * 16 + (lm & 1) * 8 + lj) * 128;
#pragma unroll
    for (int p = 0; p < 4; p++)
        bRow[p] = 16384u + (uint32_t)(warpN * 64 + p * 16 + (lm >> 1) * 8 + lj) * 128;

    float c[4][8][4];
#pragma unroll
    for (int i = 0; i < 4; i++)
#pragma unroll
        for (int j = 0; j < 8; j++)
#pragma unroll
            for (int q = 0; q < 4; q++) c[i][j][q] = 0.f;

    for (int kk = 0; kk < 16; kk++) {       // 16 x BK=64
        cp_wait1();
        __syncthreads();
        if (kk + 2 < 16) {
            int s = (kk + 2) % NSTAGE;
            int kB = (kk + 2) * 128;
            PRODUCE(s, kB);
        }
        cp_commit();   // empty group in tail keeps wait_group<1> counting uniform

        const uint32_t stgA = sb + (kk % NSTAGE) * STG;
#pragma unroll
        for (int k16 = 0; k16 < 4; k16++) {
            const uint32_t kterm = (uint32_t)k16 * 32;   // 16 fp16 = 32B per step
            uint32_t a[4][4], b[4][4];
#pragma unroll
            for (int ma = 0; ma < 4; ma++)
                ldsm4(a[ma], stgA + aRow[ma] + ((kterm + aHalf) ^ swzMask));
#pragma unroll
            for (int p = 0; p < 4; p++)
                ldsm4(b[p], stgA + bRow[p] + ((kterm + bHalf) ^ swzMask));
#pragma unroll
            for (int ma = 0; ma < 4; ma++)
#pragma unroll
                for (int nb = 0; nb < 8; nb++)
                    mma16(c[ma][nb], a[ma],
                          b[nb >> 1][(nb & 1) * 2], b[nb >> 1][(nb & 1) * 2 + 1]);
        }
    }
#undef PRODUCE

    // ---- epilogue ----
#pragma unroll
    for (int ma = 0; ma < 4; ma++) {
#pragma unroll
        for (int half = 0; half < 2; half++) {
            int grow = rowBase + warpM * 64 + ma * 16 + g + half * 8;
            if (PHASE == 1) {
                __half* hrow = g_hh + (size_t)grow * DM + colBase;
#pragma unroll
                for (int nb = 0; nb < 8; nb++) {
                    int cn = warpN * 64 + nb * 8 + tig * 2;
                    float v0 = c[ma][nb][half*2+0] + sBias[cn];
                    float v1 = c[ma][nb][half*2+1] + sBias[cn+1];
                    v0 = fmaxf(v0, 0.f); v1 = fmaxf(v1, 0.f);
                    *(uint32_t*)(hrow + cn) = f2h2(v0, v1);
                }
            } else {
                int tok = g_rowToken[grow];
                if (tok >= 0) {
                    float w = g_rowWeight[grow];
                    float* orow = Out + (size_t)tok * DM + colBase;
#pragma unroll
                    for (int nb = 0; nb < 8; nb++) {
                        int cn = warpN * 64 + nb * 8 + tig * 2;
                        float v0 = (c[ma][nb][half*2+0] + sBias[cn])   * w;
                        float v1 = (c[ma][nb][half*2+1] + sBias[cn+1]) * w;
                        asm volatile("red.global.add.v2.f32 [%0], {%1,%2};"
                                     :: "l"(orow + cn), "f"(v0), "f"(v1) : "memory");
                    }
                }
            }
        }
    }
}

// -------------------- launch -----------------------------------------------
extern "C" void kernel_launch(void* const* d_in, const int* in_sizes, int n_in,
                              void* d_out, int out_size) {
    const float* x  = (const float*)d_in[0];
    const float* gw = (const float*)d_in[1];
    const float* gb = (const float*)d_in[2];
    const float* w1 = (const float*)d_in[3];
    const float* b1 = (const float*)d_in[4];
    const float* w2 = (const float*)d_in[5];
    const float* b2 = (const float*)d_in[6];
    float* out = (float*)d_out;

    static int smemSet = 0;
    if (!smemSet) {
        cudaFuncSetAttribute(k_gemm<1>, cudaFuncAttributeMaxDynamicSharedMemorySize, SMEM_TOTAL);
        cudaFuncSetAttribute(k_gemm<2>, cudaFuncAttributeMaxDynamicSharedMemorySize, SMEM_TOTAL);
        smemSet = 1;
    }

    k_init<<<512, 256>>>(out);
    k_transpose<<<dim3(32, 32, NE), dim3(32, 8)>>>(w1, 0);
    k_transpose<<<dim3(32, 32, NE), dim3(32, 8)>>>(w2, 1);
    k_gate<<<NT / 64, 256>>>(x, gw, gb);
    k_prefix<<<1, 128>>>();
    k_scatter<<<NT * 2 / 256, 256>>>();
    dim3 gg(DM / 128, MAX_TILES);
    k_gemm<1><<<gg, 128, SMEM_TOTAL>>>(b1, nullptr);
    k_gemm<2><<<gg, 128, SMEM_TOTAL>>>(b2, out);
}

// round 10
// speedup vs baseline: 3.0422x; 1.0422x over previous
#include <cuda_runtime.h>
#include <cuda_fp16.h>
#include <cstdint>
#include <cstddef>

#define NT        32768                 // tokens = B*T
#define DM        1024
#define NE        8
#define ROWS_MAX  (2*NT + NE*128)       // 66560
#define MAX_TILES (ROWS_MAX/128)        // 520
#define STG       32768                 // per-stage: A 16KB + B 16KB (fp16, BK=64)
#define NSTAGE    3
#define SMEM_TOTAL (1024 + NSTAGE*STG)  // ~97 KB -> 2 CTAs/SM

// -------------------- device scratch (static, no allocs) --------------------
__device__ int      g_count[NE];
__device__ int      g_cursor[NE];
__device__ int      g_base[NE+1];
__device__ int      g_tileExpert[MAX_TILES];
__device__ int      g_rowToken[ROWS_MAX];
__device__ float    g_rowWeight[ROWS_MAX];
__device__ int      g_tokE[NT*2];
__device__ float    g_tokS[NT*2];
__device__ __half   g_xh[(size_t)NT * DM];         // x in fp16
__device__ __half   g_hh[(size_t)ROWS_MAX * DM];   // h in fp16
__device__ __half   g_w1t[(size_t)NE * DM * DM];   // w1^T fp16 [e][n][k]
__device__ __half   g_w2t[(size_t)NE * DM * DM];   // w2^T fp16 [e][n][k]

// -------------------- helpers ----------------------------------------------
__device__ __forceinline__ uint32_t smem_u32(const void* p) {
    uint32_t a;
    asm("{ .reg .u64 t; cvta.to.shared.u64 t, %1; cvt.u32.u64 %0, t; }" : "=r"(a) : "l"(p));
    return a;
}
__device__ __forceinline__ uint32_t f2h2(float lo, float hi) {
    uint32_t r;
    asm("cvt.rn.f16x2.f32 %0, %1, %2;" : "=r"(r) : "f"(hi), "f"(lo));
    return r;
}
__device__ __forceinline__ void cp16(uint32_t dst, const void* src, uint32_t sz) {
    asm volatile("cp.async.cg.shared.global [%0], [%1], 16, %2;"
                 :: "r"(dst), "l"(src), "r"(sz) : "memory");
}
__device__ __forceinline__ void cp_commit() { asm volatile("cp.async.commit_group;" ::: "memory"); }
__device__ __forceinline__ void cp_wait1()  { asm volatile("cp.async.wait_group 1;"  ::: "memory"); }
__device__ __forceinline__ void ldsm4(uint32_t* r, uint32_t addr) {
    asm volatile("ldmatrix.sync.aligned.m8n8.x4.shared.b16 {%0,%1,%2,%3}, [%4];"
                 : "=r"(r[0]), "=r"(r[1]), "=r"(r[2]), "=r"(r[3]) : "r"(addr));
}
__device__ __forceinline__ void mma16(float* c, const uint32_t* a, uint32_t b0, uint32_t b1) {
    asm volatile("mma.sync.aligned.m16n8k16.row.col.f32.f16.f16.f32 "
                 "{%0,%1,%2,%3}, {%4,%5,%6,%7}, {%8,%9}, {%0,%1,%2,%3};"
                 : "+f"(c[0]), "+f"(c[1]), "+f"(c[2]), "+f"(c[3])
                 : "r"(a[0]), "r"(a[1]), "r"(a[2]), "r"(a[3]),
                   "r"(b0), "r"(b1));
}

// -------------------- init --------------------------------------------------
__global__ void k_init(float* __restrict__ out) {
    int i = blockIdx.x * blockDim.x + threadIdx.x;
    int nth = gridDim.x * blockDim.x;
    if (i < NE) g_count[i] = 0;
    for (int j = i; j < ROWS_MAX; j += nth) { g_rowToken[j] = -1; g_rowWeight[j] = 0.f; }
    float4 z = make_float4(0.f, 0.f, 0.f, 0.f);
    float4* o4 = (float4*)out;
    int n4 = NT * DM / 4;
    for (int j = i; j < n4; j += nth) o4[j] = z;
}

// -------------------- w[e][k][n] -> wt[e][n][k] (fp16); z = e + which*NE ----
__global__ void k_transpose(const float* __restrict__ W1, const float* __restrict__ W2) {
    __shared__ __half t[32][34];
    int which = blockIdx.z >> 3;
    int e = blockIdx.z & 7;
    const float* W = which ? W2 : W1;
    __half* WT = which ? g_w2t : g_w1t;
    int k0 = blockIdx.x * 32, n0 = blockIdx.y * 32;
    const float* w = W + (size_t)e * DM * DM;
    __half* wt = WT + (size_t)e * DM * DM;
    for (int r = threadIdx.y; r < 32; r += 8)
        t[r][threadIdx.x] = __float2half_rn(w[(size_t)(k0 + r) * DM + n0 + threadIdx.x]);
    __syncthreads();
    for (int r = threadIdx.y; r < 32; r += 8)
        wt[(size_t)(n0 + r) * DM + k0 + threadIdx.x] = t[threadIdx.x][r];
}

// -------------------- gating: 8 tokens per warp, gw staged in smem ----------
// Each sgw row-load is reused across 8 tokens -> 8x less LDS traffic.
#define GTOK 8
__global__ void __launch_bounds__(256)
k_gate(const float* __restrict__ x,
       const float* __restrict__ gw,
       const float* __restrict__ gb) {
    __shared__ float sgw[NE * DM];
    int tid = threadIdx.x;
    for (int i = tid; i < DM * NE / 4; i += 256) {
        float4 v = ((const float4*)gw)[i];
        int k = i >> 1, e0 = (i & 1) * 4;
        sgw[(e0+0) * DM + k] = v.x;
        sgw[(e0+1) * DM + k] = v.y;
        sgw[(e0+2) * DM + k] = v.z;
        sgw[(e0+3) * DM + k] = v.w;
    }
    __syncthreads();

    int warp = tid >> 5, lane = tid & 31;
    int tokBase = (blockIdx.x * 8 + warp) * GTOK;
    const float4* xb = (const float4*)(x + (size_t)tokBase * DM);
    uint2* hb = (uint2*)(g_xh + (size_t)tokBase * DM);

    float acc[GTOK][NE];
#pragma unroll
    for (int t = 0; t < GTOK; t++)
#pragma unroll
        for (int e = 0; e < NE; e++) acc[t][e] = 0.f;

#pragma unroll 1
    for (int k4 = lane; k4 < DM / 4; k4 += 32) {
        float4 xv[GTOK];
#pragma unroll
        for (int t = 0; t < GTOK; t++) {
            xv[t] = xb[t * (DM/4) + k4];
            uint2 u;
            u.x = f2h2(xv[t].x, xv[t].y);
            u.y = f2h2(xv[t].z, xv[t].w);
            hb[t * (DM/4) + k4] = u;
        }
#pragma unroll
        for (int e = 0; e < NE; e++) {
            float4 g4 = ((const float4*)(sgw + e * DM))[k4];
#pragma unroll
            for (int t = 0; t < GTOK; t++)
                acc[t][e] += xv[t].x * g4.x + xv[t].y * g4.y
                           + xv[t].z * g4.z + xv[t].w * g4.w;
        }
    }
#pragma unroll
    for (int off = 16; off; off >>= 1)
#pragma unroll
        for (int t = 0; t < GTOK; t++)
#pragma unroll
            for (int e = 0; e < NE; e++)
                acc[t][e] += __shfl_xor_sync(0xffffffffu, acc[t][e], off);

    if (lane < GTOK) {
        int tok = tokBase + lane;
        float a[NE];
#pragma unroll
        for (int e = 0; e < NE; e++) a[e] = acc[lane][e] + gb[e];
        int e0 = 0; float s0 = a[0];
#pragma unroll
        for (int e = 1; e < NE; e++) if (a[e] > s0) { s0 = a[e]; e0 = e; }
        int e1 = -1; float s1 = -3.4e38f;
#pragma unroll
        for (int e = 0; e < NE; e++) if (e != e0 && a[e] > s1) { s1 = a[e]; e1 = e; }
        g_tokE[2*tok]   = e0;  g_tokS[2*tok]   = s0;
        g_tokE[2*tok+1] = e1;  g_tokS[2*tok+1] = s1;
        atomicAdd(&g_count[e0], 1);
        atomicAdd(&g_count[e1], 1);
    }
}

// -------------------- prefix (128-aligned) + tile->expert -------------------
__global__ void k_prefix() {
    if (threadIdx.x == 0) {
        int b = 0; g_base[0] = 0;
        for (int e = 0; e < NE; e++) {
            g_cursor[e] = b;
            b += ((g_count[e] + 127) >> 7) << 7;
            g_base[e+1] = b;
        }
    }
    __syncthreads();
    for (int t = threadIdx.x; t < MAX_TILES; t += blockDim.x) {
        int r = t << 7;
        int e = -1;
        for (int q = 0; q < NE; q++)
            if (r >= g_base[q] && r < g_base[q+1]) e = q;
        g_tileExpert[t] = e;
    }
}

__global__ void k_scatter() {
    int i = blockIdx.x * blockDim.x + threadIdx.x;
    if (i >= NT * 2) return;
    int e = g_tokE[i];
    int p = atomicAdd(&g_cursor[e], 1);
    g_rowToken[p]  = i >> 1;
    g_rowWeight[p] = g_tokS[i];
}

// -------------------- pipelined fp16 grouped GEMM ---------------------------
// CTA 128x128, 128 threads (4 warps 2x2, warp tile 64x64), BK=64 (128B rows),
// 3-stage cp.async, ldmatrix fragments, m16n8k16 f16 mma, 2 CTAs/SM.
template<int PHASE>
__global__ void __launch_bounds__(128, 2)
k_gemm(const float* __restrict__ Bias, float* __restrict__ Out) {
    extern __shared__ char smem[];
    int e = g_tileExpert[blockIdx.y];
    if (e < 0) return;
    const int rowBase = blockIdx.y * 128, colBase = blockIdx.x * 128;
    const int tid = threadIdx.x, lane = tid & 31, wid = tid >> 5;

    float* sBias = (float*)smem;
    sBias[tid] = Bias[e * DM + colBase + tid];

    const uint32_t sb = smem_u32(smem) + 1024;

    // ---- producer: 8 A-chunks + 8 B-chunks (16B) per thread per stage ----
    const int tr = tid >> 3, ch = tid & 7;                 // tr 0..15, ch 0..7
    const uint32_t dOff0 = tr * 128 + ((ch * 16) ^ ((tr & 7) << 4));
    const char* wT = (const char*)((PHASE == 1 ? g_w1t : g_w2t) + ((size_t)e << 20));
    const char* aBase = (PHASE == 1) ? (const char*)g_xh
                                     : (const char*)(g_hh + (size_t)rowBase * DM);
    uint32_t aOff[8], aSz[8], bOff[8];
#pragma unroll
    for (int i = 0; i < 8; i++) {
        int row = tr + 16 * i;
        if (PHASE == 1) {
            int tok = g_rowToken[rowBase + row];
            aOff[i] = (uint32_t)(tok < 0 ? 0 : tok) * 2048u + ch * 16;
            aSz[i]  = (tok < 0) ? 0u : 16u;
        } else {
            aOff[i] = (uint32_t)row * 2048u + ch * 16;
            aSz[i]  = 16u;
        }
        bOff[i] = (uint32_t)(colBase + row) * 2048u + ch * 16;
    }

#define PRODUCE(STAGE, KB)                                                      \
    {                                                                           \
        uint32_t base_ = sb + (STAGE) * STG;                                    \
        _Pragma("unroll")                                                       \
        for (int i_ = 0; i_ < 8; i_++) {                                        \
            cp16(base_ + dOff0 + i_ * 2048,         aBase + aOff[i_] + (KB), aSz[i_]); \
            cp16(base_ + 16384 + dOff0 + i_ * 2048, wT + bOff[i_] + (KB), 16); \
        }                                                                       \
    }

    PRODUCE(0, 0);    cp_commit();
    PRODUCE(1, 128);  cp_commit();

    // ---- consumer: ldmatrix addressing ----
    const int g = lane >> 2, tig = lane & 3;
    const int warpM = wid >> 1, warpN = wid & 1;
    const int lm = lane >> 3, lj = lane & 7;       // matrix idx, row within matrix
    const uint32_t swzMask = (uint32_t)lj << 4;
    const uint32_t aHalf = (uint32_t)(lm >> 1) << 4;   // A: m0,m1 khalf0; m2,m3 khalf1
    const uint32_t bHalf = (uint32_t)(lm & 1) << 4;    // B: m0,m2 khalf0; m1,m3 khalf1
    uint32_t aRow[4], bRow[4];
#pragma unroll
    for (int ma = 0; ma < 4; ma++)
        aRow[ma] = (uint32_t)(warpM * 64 + ma * 16 + (lm & 1) * 8 + lj) * 128;
#pragma unroll
    for (int p = 0; p < 4; p++)
        bRow[p] = 16384u + (uint32_t)(warpN * 64 + p * 16 + (lm >> 1) * 8 + lj) * 128;

    float c[4][8][4];
#pragma unroll
    for (int i = 0; i < 4; i++)
#pragma unroll
        for (int j = 0; j < 8; j++)
#pragma unroll
            for (int q = 0; q < 4; q++) c[i][j][q] = 0.f;

    for (int kk = 0; kk < 16; kk++) {       // 16 x BK=64
        cp_wait1();
        __syncthreads();
        if (kk + 2 < 16) {
            int s = (kk + 2) % NSTAGE;
            int kB = (kk + 2) * 128;
            PRODUCE(s, kB);
        }
        cp_commit();   // empty group in tail keeps wait_group<1> counting uniform

        const uint32_t stgA = sb + (kk % NSTAGE) * STG;
#pragma unroll
        for (int k16 = 0; k16 < 4; k16++) {
            const uint32_t kterm = (uint32_t)k16 * 32;   // 16 fp16 = 32B per step
            uint32_t a[4][4], b[4][4];
#pragma unroll
            for (int ma = 0; ma < 4; ma++)
                ldsm4(a[ma], stgA + aRow[ma] + ((kterm + aHalf) ^ swzMask));
#pragma unroll
            for (int p = 0; p < 4; p++)
                ldsm4(b[p], stgA + bRow[p] + ((kterm + bHalf) ^ swzMask));
#pragma unroll
            for (int ma = 0; ma < 4; ma++)
#pragma unroll
                for (int nb = 0; nb < 8; nb++)
                    mma16(c[ma][nb], a[ma],
                          b[nb >> 1][(nb & 1) * 2], b[nb >> 1][(nb & 1) * 2 + 1]);
        }
    }
#undef PRODUCE

    // ---- epilogue ----
#pragma unroll
    for (int ma = 0; ma < 4; ma++) {
#pragma unroll
        for (int half = 0; half < 2; half++) {
            int grow = rowBase + warpM * 64 + ma * 16 + g + half * 8;
            if (PHASE == 1) {
                __half* hrow = g_hh + (size_t)grow * DM + colBase;
#pragma unroll
                for (int nb = 0; nb < 8; nb++) {
                    int cn = warpN * 64 + nb * 8 + tig * 2;
                    float v0 = c[ma][nb][half*2+0] + sBias[cn];
                    float v1 = c[ma][nb][half*2+1] + sBias[cn+1];
                    v0 = fmaxf(v0, 0.f); v1 = fmaxf(v1, 0.f);
                    *(uint32_t*)(hrow + cn) = f2h2(v0, v1);
                }
            } else {
                int tok = g_rowToken[grow];
                if (tok >= 0) {
                    float w = g_rowWeight[grow];
                    float* orow = Out + (size_t)tok * DM + colBase;
#pragma unroll
                    for (int nb = 0; nb < 8; nb++) {
                        int cn = warpN * 64 + nb * 8 + tig * 2;
                        float v0 = (c[ma][nb][half*2+0] + sBias[cn])   * w;
                        float v1 = (c[ma][nb][half*2+1] + sBias[cn+1]) * w;
                        asm volatile("red.global.add.v2.f32 [%0], {%1,%2};"
                                     :: "l"(orow + cn), "f"(v0), "f"(v1) : "memory");
                    }
                }
            }
        }
    }
}

// -------------------- launch -----------------------------------------------
extern "C" void kernel_launch(void* const* d_in, const int* in_sizes, int n_in,
                              void* d_out, int out_size) {
    const float* x  = (const float*)d_in[0];
    const float* gw = (const float*)d_in[1];
    const float* gb = (const float*)d_in[2];
    const float* w1 = (const float*)d_in[3];
    const float* b1 = (const float*)d_in[4];
    const float* w2 = (const float*)d_in[5];
    const float* b2 = (const float*)d_in[6];
    float* out = (float*)d_out;

    static int smemSet = 0;
    if (!smemSet) {
        cudaFuncSetAttribute(k_gemm<1>, cudaFuncAttributeMaxDynamicSharedMemorySize, SMEM_TOTAL);
        cudaFuncSetAttribute(k_gemm<2>, cudaFuncAttributeMaxDynamicSharedMemorySize, SMEM_TOTAL);
        smemSet = 1;
    }

    k_init<<<1024, 256>>>(out);
    k_transpose<<<dim3(32, 32, 2*NE), dim3(32, 8)>>>(w1, w2);
    k_gate<<<NT / 64, 256>>>(x, gw, gb);
    k_prefix<<<1, 128>>>();
    k_scatter<<<NT * 2 / 256, 256>>>();
    dim3 gg(DM / 128, MAX_TILES);
    k_gemm<1><<<gg, 128, SMEM_TOTAL>>>(b1, nullptr);
    k_gemm<2><<<gg, 128, SMEM_TOTAL>>>(b2, out);
}

// round 11
// speedup vs baseline: 3.1262x; 1.0276x over previous
#include <cuda_runtime.h>
#include <cuda_fp16.h>
#include <cstdint>
#include <cstddef>

#define NT        32768                 // tokens = B*T
#define DM        1024
#define NE        8
#define ROWS_MAX  (2*NT + NE*128)       // 66560
#define MAX_TILES (ROWS_MAX/128)        // 520
#define STG       32768                 // per-stage: A 16KB + B 16KB (fp16, BK=64)
#define NSTAGE    3
#define SMEM_TOTAL (1024 + NSTAGE*STG)  // ~97 KB -> 2 CTAs/SM

// -------------------- device scratch (static, no allocs) --------------------
__device__ int      g_count[NE];
__device__ int      g_cursor[NE];
__device__ int      g_base[NE+1];
__device__ int      g_tileExpert[MAX_TILES];
__device__ int      g_rowToken[ROWS_MAX];
__device__ float    g_rowWeight[ROWS_MAX];
__device__ int      g_tokE[NT*2];
__device__ float    g_tokS[NT*2];
__device__ __half   g_xh[(size_t)NT * DM];         // x in fp16
__device__ __half   g_hh[(size_t)ROWS_MAX * DM];   // h in fp16
__device__ __half   g_w1t[(size_t)NE * DM * DM];   // w1^T fp16 [e][n][k]
__device__ __half   g_w2t[(size_t)NE * DM * DM];   // w2^T fp16 [e][n][k]

// -------------------- helpers ----------------------------------------------
__device__ __forceinline__ uint32_t smem_u32(const void* p) {
    uint32_t a;
    asm("{ .reg .u64 t; cvta.to.shared.u64 t, %1; cvt.u32.u64 %0, t; }" : "=r"(a) : "l"(p));
    return a;
}
__device__ __forceinline__ uint32_t f2h2(float lo, float hi) {
    uint32_t r;
    asm("cvt.rn.f16x2.f32 %0, %1, %2;" : "=r"(r) : "f"(hi), "f"(lo));
    return r;
}
__device__ __forceinline__ void cp16(uint32_t dst, const void* src, uint32_t sz) {
    asm volatile("cp.async.cg.shared.global [%0], [%1], 16, %2;"
                 :: "r"(dst), "l"(src), "r"(sz) : "memory");
}
__device__ __forceinline__ void cp_commit() { asm volatile("cp.async.commit_group;" ::: "memory"); }
__device__ __forceinline__ void cp_wait1()  { asm volatile("cp.async.wait_group 1;"  ::: "memory"); }
__device__ __forceinline__ void ldsm4(uint32_t* r, uint32_t addr) {
    asm volatile("ldmatrix.sync.aligned.m8n8.x4.shared.b16 {%0,%1,%2,%3}, [%4];"
                 : "=r"(r[0]), "=r"(r[1]), "=r"(r[2]), "=r"(r[3]) : "r"(addr));
}
__device__ __forceinline__ void mma16(float* c, const uint32_t* a, uint32_t b0, uint32_t b1) {
    asm volatile("mma.sync.aligned.m16n8k16.row.col.f32.f16.f16.f32 "
                 "{%0,%1,%2,%3}, {%4,%5,%6,%7}, {%8,%9}, {%0,%1,%2,%3};"
                 : "+f"(c[0]), "+f"(c[1]), "+f"(c[2]), "+f"(c[3])
                 : "r"(a[0]), "r"(a[1]), "r"(a[2]), "r"(a[3]),
                   "r"(b0), "r"(b1));
}

// -------------------- init --------------------------------------------------
__global__ void k_init(float* __restrict__ out) {
    int i = blockIdx.x * blockDim.x + threadIdx.x;
    int nth = gridDim.x * blockDim.x;
    if (i < NE) g_count[i] = 0;
    for (int j = i; j < ROWS_MAX; j += nth) { g_rowToken[j] = -1; g_rowWeight[j] = 0.f; }
    float4 z = make_float4(0.f, 0.f, 0.f, 0.f);
    float4* o4 = (float4*)out;
    int n4 = NT * DM / 4;
    for (int j = i; j < n4; j += nth) o4[j] = z;
}

// -------------------- w[e][k][n] -> wt[e][n][k] (fp16), 64x64 tiles ---------
// float4 reads / uint2 (4xfp16) writes, both 128B-coalesced. z = e + which*NE.
__global__ void __launch_bounds__(256)
k_transpose(const float* __restrict__ W1, const float* __restrict__ W2) {
    __shared__ __half s[64][68];
    int which = blockIdx.z >> 3;
    int e = blockIdx.z & 7;
    const float* w = (which ? W2 : W1) + (size_t)e * DM * DM;
    __half* wt = (which ? g_w2t : g_w1t) + (size_t)e * DM * DM;
    int k0 = blockIdx.x * 64, n0 = blockIdx.y * 64;

    int c4 = threadIdx.x & 15;          // n group (4 floats)
    int r  = threadIdx.x >> 4;          // 0..15
#pragma unroll
    for (int i = 0; i < 4; i++) {
        int kr = r + 16 * i;
        float4 v = *(const float4*)(w + (size_t)(k0 + kr) * DM + n0 + c4 * 4);
        s[c4 * 4 + 0][kr] = __float2half_rn(v.x);
        s[c4 * 4 + 1][kr] = __float2half_rn(v.y);
        s[c4 * 4 + 2][kr] = __float2half_rn(v.z);
        s[c4 * 4 + 3][kr] = __float2half_rn(v.w);
    }
    __syncthreads();
#pragma unroll
    for (int i = 0; i < 4; i++) {
        int nr = r + 16 * i;
        *(uint2*)(wt + (size_t)(n0 + nr) * DM + k0 + c4 * 4) =
            *(const uint2*)&s[nr][c4 * 4];
    }
}

// -------------------- gating: 8 tokens per warp, gw staged in smem ----------
#define GTOK 8
__global__ void __launch_bounds__(256)
k_gate(const float* __restrict__ x,
       const float* __restrict__ gw,
       const float* __restrict__ gb) {
    __shared__ float sgw[NE * DM];
    int tid = threadIdx.x;
    for (int i = tid; i < DM * NE / 4; i += 256) {
        float4 v = ((const float4*)gw)[i];
        int k = i >> 1, e0 = (i & 1) * 4;
        sgw[(e0+0) * DM + k] = v.x;
        sgw[(e0+1) * DM + k] = v.y;
        sgw[(e0+2) * DM + k] = v.z;
        sgw[(e0+3) * DM + k] = v.w;
    }
    __syncthreads();

    int warp = tid >> 5, lane = tid & 31;
    int tokBase = (blockIdx.x * 8 + warp) * GTOK;
    const float4* xb = (const float4*)(x + (size_t)tokBase * DM);
    uint2* hb = (uint2*)(g_xh + (size_t)tokBase * DM);

    float acc[GTOK][NE];
#pragma unroll
    for (int t = 0; t < GTOK; t++)
#pragma unroll
        for (int e = 0; e < NE; e++) acc[t][e] = 0.f;

#pragma unroll 1
    for (int k4 = lane; k4 < DM / 4; k4 += 32) {
        float4 xv[GTOK];
#pragma unroll
        for (int t = 0; t < GTOK; t++) {
            xv[t] = xb[t * (DM/4) + k4];
            uint2 u;
            u.x = f2h2(xv[t].x, xv[t].y);
            u.y = f2h2(xv[t].z, xv[t].w);
            hb[t * (DM/4) + k4] = u;
        }
#pragma unroll
        for (int e = 0; e < NE; e++) {
            float4 g4 = ((const float4*)(sgw + e * DM))[k4];
#pragma unroll
            for (int t = 0; t < GTOK; t++)
                acc[t][e] += xv[t].x * g4.x + xv[t].y * g4.y
                           + xv[t].z * g4.z + xv[t].w * g4.w;
        }
    }
#pragma unroll
    for (int off = 16; off; off >>= 1)
#pragma unroll
        for (int t = 0; t < GTOK; t++)
#pragma unroll
            for (int e = 0; e < NE; e++)
                acc[t][e] += __shfl_xor_sync(0xffffffffu, acc[t][e], off);

    if (lane < GTOK) {
        int tok = tokBase + lane;
        float a[NE];
#pragma unroll
        for (int e = 0; e < NE; e++) a[e] = acc[lane][e] + gb[e];
        int e0 = 0; float s0 = a[0];
#pragma unroll
        for (int e = 1; e < NE; e++) if (a[e] > s0) { s0 = a[e]; e0 = e; }
        int e1 = -1; float s1 = -3.4e38f;
#pragma unroll
        for (int e = 0; e < NE; e++) if (e != e0 && a[e] > s1) { s1 = a[e]; e1 = e; }
        g_tokE[2*tok]   = e0;  g_tokS[2*tok]   = s0;
        g_tokE[2*tok+1] = e1;  g_tokS[2*tok+1] = s1;
        atomicAdd(&g_count[e0], 1);
        atomicAdd(&g_count[e1], 1);
    }
}

// -------------------- prefix (128-aligned) + tile->expert -------------------
__global__ void k_prefix() {
    __shared__ int base[NE+1];
    if (threadIdx.x == 0) {
        int b = 0; base[0] = 0; g_base[0] = 0;
        for (int e = 0; e < NE; e++) {
            g_cursor[e] = b;
            b += ((g_count[e] + 127) >> 7) << 7;
            base[e+1] = b; g_base[e+1] = b;
        }
    }
    __syncthreads();
    for (int t = threadIdx.x; t < MAX_TILES; t += blockDim.x) {
        int r = t << 7;
        int e = -1;
#pragma unroll
        for (int q = 0; q < NE; q++)
            if (r >= base[q] && r < base[q+1]) e = q;
        g_tileExpert[t] = e;
    }
}

__global__ void k_scatter() {
    int i = blockIdx.x * blockDim.x + threadIdx.x;
    if (i >= NT * 2) return;
    int e = g_tokE[i];
    int p = atomicAdd(&g_cursor[e], 1);
    g_rowToken[p]  = i >> 1;
    g_rowWeight[p] = g_tokS[i];
}

// -------------------- pipelined fp16 grouped GEMM ---------------------------
// CTA 128x128, 128 threads (4 warps 2x2, warp tile 64x64), BK=64 (128B rows),
// 3-stage cp.async, ldmatrix fragments, m16n8k16 f16 mma, 2 CTAs/SM.
template<int PHASE>
__global__ void __launch_bounds__(128, 2)
k_gemm(const float* __restrict__ Bias, float* __restrict__ Out) {
    extern __shared__ char smem[];
    int e = g_tileExpert[blockIdx.y];
    if (e < 0) return;
    const int rowBase = blockIdx.y * 128, colBase = blockIdx.x * 128;
    const int tid = threadIdx.x, lane = tid & 31, wid = tid >> 5;

    float* sBias = (float*)smem;
    sBias[tid] = Bias[e * DM + colBase + tid];

    const uint32_t sb = smem_u32(smem) + 1024;

    // ---- producer: 8 A-chunks + 8 B-chunks (16B) per thread per stage ----
    const int tr = tid >> 3, ch = tid & 7;                 // tr 0..15, ch 0..7
    const uint32_t dOff0 = tr * 128 + ((ch * 16) ^ ((tr & 7) << 4));
    const char* wT = (const char*)((PHASE == 1 ? g_w1t : g_w2t) + ((size_t)e << 20));
    const char* aBase = (PHASE == 1) ? (const char*)g_xh
                                     : (const char*)(g_hh + (size_t)rowBase * DM);
    uint32_t aOff[8], aSz[8], bOff[8];
#pragma unroll
    for (int i = 0; i < 8; i++) {
        int row = tr + 16 * i;
        if (PHASE == 1) {
            int tok = g_rowToken[rowBase + row];
            aOff[i] = (uint32_t)(tok < 0 ? 0 : tok) * 2048u + ch * 16;
            aSz[i]  = (tok < 0) ? 0u : 16u;
        } else {
            aOff[i] = (uint32_t)row * 2048u + ch * 16;
            aSz[i]  = 16u;
        }
        bOff[i] = (uint32_t)(colBase + row) * 2048u + ch * 16;
    }

#define PRODUCE(STAGE, KB)                                                      \
    {                                                                           \
        uint32_t base_ = sb + (STAGE) * STG;                                    \
        _Pragma("unroll")                                                       \
        for (int i_ = 0; i_ < 8; i_++) {                                        \
            cp16(base_ + dOff0 + i_ * 2048,         aBase + aOff[i_] + (KB), aSz[i_]); \
            cp16(base_ + 16384 + dOff0 + i_ * 2048, wT + bOff[i_] + (KB), 16); \
        }                                                                       \
    }

    PRODUCE(0, 0);    cp_commit();
    PRODUCE(1, 128);  cp_commit();

    // ---- consumer: ldmatrix addressing ----
    const int g = lane >> 2, tig = lane & 3;
    const int warpM = wid >> 1, warpN = wid & 1;
    const int lm = lane >> 3, lj = lane & 7;       // matrix idx, row within matrix
    const uint32_t swzMask = (uint32_t)lj << 4;
    const uint32_t aHalf = (uint32_t)(lm >> 1) << 4;   // A: m0,m1 khalf0; m2,m3 khalf1
    const uint32_t bHalf = (uint32_t)(lm & 1) << 4;    // B: m0,m2 khalf0; m1,m3 khalf1
    uint32_t aRow[4], bRow[4];
#pragma unroll
    for (int ma = 0; ma < 4; ma++)
        aRow[ma] = (uint32_t)(warpM * 64 + ma * 16 + (lm & 1) * 8 + lj) * 128;
#pragma unroll
    for (int p = 0; p < 4; p++)
        bRow[p] = 16384u + (uint32_t)(warpN * 64 + p * 16 + (lm >> 1) * 8 + lj) * 128;

    float c[4][8][4];
#pragma unroll
    for (int i = 0; i < 4; i++)
#pragma unroll
        for (int j = 0; j < 8; j++)
#pragma unroll
            for (int q = 0; q < 4; q++) c[i][j][q] = 0.f;

    for (int kk = 0; kk < 16; kk++) {       // 16 x BK=64
        cp_wait1();
        __syncthreads();
        if (kk + 2 < 16) {
            int s = (kk + 2) % NSTAGE;
            int kB = (kk + 2) * 128;
            PRODUCE(s, kB);
        }
        cp_commit();   // empty group in tail keeps wait_group<1> counting uniform

        const uint32_t stgA = sb + (kk % NSTAGE) * STG;
#pragma unroll
        for (int k16 = 0; k16 < 4; k16++) {
            const uint32_t kterm = (uint32_t)k16 * 32;   // 16 fp16 = 32B per step
            uint32_t a[4][4], b[4][4];
#pragma unroll
            for (int ma = 0; ma < 4; ma++)
                ldsm4(a[ma], stgA + aRow[ma] + ((kterm + aHalf) ^ swzMask));
#pragma unroll
            for (int p = 0; p < 4; p++)
                ldsm4(b[p], stgA + bRow[p] + ((kterm + bHalf) ^ swzMask));
#pragma unroll
            for (int ma = 0; ma < 4; ma++)
#pragma unroll
                for (int nb = 0; nb < 8; nb++)
                    mma16(c[ma][nb], a[ma],
                          b[nb >> 1][(nb & 1) * 2], b[nb >> 1][(nb & 1) * 2 + 1]);
        }
    }
#undef PRODUCE

    // ---- epilogue ----
#pragma unroll
    for (int ma = 0; ma < 4; ma++) {
#pragma unroll
        for (int half = 0; half < 2; half++) {
            int grow = rowBase + warpM * 64 + ma * 16 + g + half * 8;
            if (PHASE == 1) {
                __half* hrow = g_hh + (size_t)grow * DM + colBase;
#pragma unroll
                for (int nb = 0; nb < 8; nb++) {
                    int cn = warpN * 64 + nb * 8 + tig * 2;
                    float v0 = c[ma][nb][half*2+0] + sBias[cn];
                    float v1 = c[ma][nb][half*2+1] + sBias[cn+1];
                    v0 = fmaxf(v0, 0.f); v1 = fmaxf(v1, 0.f);
                    *(uint32_t*)(hrow + cn) = f2h2(v0, v1);
                }
            } else {
                int tok = g_rowToken[grow];
                if (tok >= 0) {
                    float w = g_rowWeight[grow];
                    float* orow = Out + (size_t)tok * DM + colBase;
#pragma unroll
                    for (int nb = 0; nb < 8; nb++) {
                        int cn = warpN * 64 + nb * 8 + tig * 2;
                        float v0 = (c[ma][nb][half*2+0] + sBias[cn])   * w;
                        float v1 = (c[ma][nb][half*2+1] + sBias[cn+1]) * w;
                        asm volatile("red.global.add.v2.f32 [%0], {%1,%2};"
                                     :: "l"(orow + cn), "f"(v0), "f"(v1) : "memory");
                    }
                }
            }
        }
    }
}

// -------------------- launch -----------------------------------------------
extern "C" void kernel_launch(void* const* d_in, const int* in_sizes, int n_in,
                              void* d_out, int out_size) {
    const float* x  = (const float*)d_in[0];
    const float* gw = (const float*)d_in[1];
    const float* gb = (const float*)d_in[2];
    const float* w1 = (const float*)d_in[3];
    const float* b1 = (const float*)d_in[4];
    const float* w2 = (const float*)d_in[5];
    const float* b2 = (const float*)d_in[6];
    float* out = (float*)d_out;

    static int smemSet = 0;
    if (!smemSet) {
        cudaFuncSetAttribute(k_gemm<1>, cudaFuncAttributeMaxDynamicSharedMemorySize, SMEM_TOTAL);
        cudaFuncSetAttribute(k_gemm<2>, cudaFuncAttributeMaxDynamicSharedMemorySize, SMEM_TOTAL);
        smemSet = 1;
    }

    k_init<<<2048, 256>>>(out);
    k_transpose<<<dim3(16, 16, 2*NE), 256>>>(w1, w2);
    k_gate<<<NT / 64, 256>>>(x, gw, gb);
    k_prefix<<<1, 128>>>();
    k_scatter<<<NT * 2 / 256, 256>>>();
    dim3 gg(DM / 128, MAX_TILES);
    k_gemm<1><<<gg, 128, SMEM_TOTAL>>>(b1, nullptr);
    k_gemm<2><<<gg, 128, SMEM_TOTAL>>>(b2, out);
}

// round 12
// speedup vs baseline: 3.1407x; 1.0046x over previous
#include <cuda_runtime.h>
#include <cuda_fp16.h>
#include <cstdint>
#include <cstddef>

#define NT        32768                 // tokens = B*T
#define DM        1024
#define NE        8
#define ROWS_MAX  (2*NT + NE*128)       // 66560
#define MAX_TILES (ROWS_MAX/128)        // 520
#define STG       32768                 // per-stage: A 16KB + B 16KB (fp16, BK=64)
#define NSTAGE    3
#define SMEM_TOTAL (1024 + NSTAGE*STG)  // ~97 KB -> 2 CTAs/SM

// -------------------- device scratch (static, no allocs) --------------------
__device__ int      g_count[NE];
__device__ int      g_cursor[NE];
__device__ int      g_base[NE+1];
__device__ int      g_tileExpert[MAX_TILES];
__device__ int      g_rowToken[ROWS_MAX];
__device__ float    g_rowWeight[ROWS_MAX];
__device__ int      g_tokE[NT*2];
__device__ float    g_tokS[NT*2];
__device__ __half   g_xh[(size_t)NT * DM];         // x in fp16
__device__ __half   g_hh[(size_t)ROWS_MAX * DM];   // h in fp16
__device__ __half   g_w1t[(size_t)NE * DM * DM];   // w1^T fp16 [e][n][k]
__device__ __half   g_w2t[(size_t)NE * DM * DM];   // w2^T fp16 [e][n][k]

// -------------------- helpers ----------------------------------------------
__device__ __forceinline__ uint32_t smem_u32(const void* p) {
    uint32_t a;
    asm("{ .reg .u64 t; cvta.to.shared.u64 t, %1; cvt.u32.u64 %0, t; }" : "=r"(a) : "l"(p));
    return a;
}
__device__ __forceinline__ uint32_t f2h2(float lo, float hi) {
    uint32_t r;
    asm("cvt.rn.f16x2.f32 %0, %1, %2;" : "=r"(r) : "f"(hi), "f"(lo));
    return r;
}
__device__ __forceinline__ void cp16(uint32_t dst, const void* src, uint32_t sz) {
    asm volatile("cp.async.cg.shared.global [%0], [%1], 16, %2;"
                 :: "r"(dst), "l"(src), "r"(sz) : "memory");
}
__device__ __forceinline__ void cp_commit() { asm volatile("cp.async.commit_group;" ::: "memory"); }
__device__ __forceinline__ void cp_wait1()  { asm volatile("cp.async.wait_group 1;"  ::: "memory"); }
__device__ __forceinline__ void ldsm4(uint32_t* r, uint32_t addr) {
    asm volatile("ldmatrix.sync.aligned.m8n8.x4.shared.b16 {%0,%1,%2,%3}, [%4];"
                 : "=r"(r[0]), "=r"(r[1]), "=r"(r[2]), "=r"(r[3]) : "r"(addr));
}
__device__ __forceinline__ void mma16(float* c, const uint32_t* a, uint32_t b0, uint32_t b1) {
    asm volatile("mma.sync.aligned.m16n8k16.row.col.f32.f16.f16.f32 "
                 "{%0,%1,%2,%3}, {%4,%5,%6,%7}, {%8,%9}, {%0,%1,%2,%3};"
                 : "+f"(c[0]), "+f"(c[1]), "+f"(c[2]), "+f"(c[3])
                 : "r"(a[0]), "r"(a[1]), "r"(a[2]), "r"(a[3]),
                   "r"(b0), "r"(b1));
}

// -------------------- fused prep: transpose (z<16) + init (z>=16) -----------
// z in [0,16): w[e][k][n] -> wt[e][n][k] fp16, 64x64 tiles, coalesced IO.
// z in [16,24): zero out[], poison rowToken/rowWeight, zero counters.
__global__ void __launch_bounds__(256)
k_prep(const float* __restrict__ W1, const float* __restrict__ W2,
       float* __restrict__ out) {
    if (blockIdx.z < 16) {
        __shared__ __half s[64][68];
        int which = blockIdx.z >> 3;
        int e = blockIdx.z & 7;
        const float* w = (which ? W2 : W1) + (size_t)e * DM * DM;
        __half* wt = (which ? g_w2t : g_w1t) + (size_t)e * DM * DM;
        int k0 = blockIdx.x * 64, n0 = blockIdx.y * 64;
        int c4 = threadIdx.x & 15;
        int r  = threadIdx.x >> 4;
#pragma unroll
        for (int i = 0; i < 4; i++) {
            int kr = r + 16 * i;
            float4 v = *(const float4*)(w + (size_t)(k0 + kr) * DM + n0 + c4 * 4);
            s[c4 * 4 + 0][kr] = __float2half_rn(v.x);
            s[c4 * 4 + 1][kr] = __float2half_rn(v.y);
            s[c4 * 4 + 2][kr] = __float2half_rn(v.z);
            s[c4 * 4 + 3][kr] = __float2half_rn(v.w);
        }
        __syncthreads();
#pragma unroll
        for (int i = 0; i < 4; i++) {
            int nr = r + 16 * i;
            *(uint2*)(wt + (size_t)(n0 + nr) * DM + k0 + c4 * 4) =
                *(const uint2*)&s[nr][c4 * 4];
        }
    } else {
        int slice = blockIdx.z - 16;                      // 0..7
        int cta = blockIdx.y * 16 + blockIdx.x;           // 0..255
        int gid = (slice * 256 + cta) * 256 + threadIdx.x;
        const int nth = 8 * 256 * 256;                    // 524288
        if (gid < NE) g_count[gid] = 0;
        for (int j = gid; j < ROWS_MAX; j += nth) { g_rowToken[j] = -1; g_rowWeight[j] = 0.f; }
        float4 z4 = make_float4(0.f, 0.f, 0.f, 0.f);
        float4* o4 = (float4*)out;
        int n4 = NT * DM / 4;
        for (int j = gid; j < n4; j += nth) o4[j] = z4;
    }
}

// -------------------- gating: 8 tokens per warp, gw staged in smem ----------
#define GTOK 8
__global__ void __launch_bounds__(256)
k_gate(const float* __restrict__ x,
       const float* __restrict__ gw,
       const float* __restrict__ gb) {
    __shared__ float sgw[NE * DM];
    int tid = threadIdx.x;
    for (int i = tid; i < DM * NE / 4; i += 256) {
        float4 v = ((const float4*)gw)[i];
        int k = i >> 1, e0 = (i & 1) * 4;
        sgw[(e0+0) * DM + k] = v.x;
        sgw[(e0+1) * DM + k] = v.y;
        sgw[(e0+2) * DM + k] = v.z;
        sgw[(e0+3) * DM + k] = v.w;
    }
    __syncthreads();

    int warp = tid >> 5, lane = tid & 31;
    int tokBase = (blockIdx.x * 8 + warp) * GTOK;
    const float4* xb = (const float4*)(x + (size_t)tokBase * DM);
    uint2* hb = (uint2*)(g_xh + (size_t)tokBase * DM);

    float acc[GTOK][NE];
#pragma unroll
    for (int t = 0; t < GTOK; t++)
#pragma unroll
        for (int e = 0; e < NE; e++) acc[t][e] = 0.f;

#pragma unroll 1
    for (int k4 = lane; k4 < DM / 4; k4 += 32) {
        float4 xv[GTOK];
#pragma unroll
        for (int t = 0; t < GTOK; t++) {
            xv[t] = xb[t * (DM/4) + k4];
            uint2 u;
            u.x = f2h2(xv[t].x, xv[t].y);
            u.y = f2h2(xv[t].z, xv[t].w);
            hb[t * (DM/4) + k4] = u;
        }
#pragma unroll
        for (int e = 0; e < NE; e++) {
            float4 g4 = ((const float4*)(sgw + e * DM))[k4];
#pragma unroll
            for (int t = 0; t < GTOK; t++)
                acc[t][e] += xv[t].x * g4.x + xv[t].y * g4.y
                           + xv[t].z * g4.z + xv[t].w * g4.w;
        }
    }
#pragma unroll
    for (int off = 16; off; off >>= 1)
#pragma unroll
        for (int t = 0; t < GTOK; t++)
#pragma unroll
            for (int e = 0; e < NE; e++)
                acc[t][e] += __shfl_xor_sync(0xffffffffu, acc[t][e], off);

    if (lane < GTOK) {
        int tok = tokBase + lane;
        float a[NE];
#pragma unroll
        for (int e = 0; e < NE; e++) a[e] = acc[lane][e] + gb[e];
        int e0 = 0; float s0 = a[0];
#pragma unroll
        for (int e = 1; e < NE; e++) if (a[e] > s0) { s0 = a[e]; e0 = e; }
        int e1 = -1; float s1 = -3.4e38f;
#pragma unroll
        for (int e = 0; e < NE; e++) if (e != e0 && a[e] > s1) { s1 = a[e]; e1 = e; }
        g_tokE[2*tok]   = e0;  g_tokS[2*tok]   = s0;
        g_tokE[2*tok+1] = e1;  g_tokS[2*tok+1] = s1;
        atomicAdd(&g_count[e0], 1);
        atomicAdd(&g_count[e1], 1);
    }
}

// -------------------- prefix (128-aligned) + tile->expert -------------------
__global__ void k_prefix() {
    __shared__ int base[NE+1];
    if (threadIdx.x == 0) {
        int b = 0; base[0] = 0; g_base[0] = 0;
        for (int e = 0; e < NE; e++) {
            g_cursor[e] = b;
            b += ((g_count[e] + 127) >> 7) << 7;
            base[e+1] = b; g_base[e+1] = b;
        }
    }
    __syncthreads();
    for (int t = threadIdx.x; t < MAX_TILES; t += blockDim.x) {
        int r = t << 7;
        int e = -1;
#pragma unroll
        for (int q = 0; q < NE; q++)
            if (r >= base[q] && r < base[q+1]) e = q;
        g_tileExpert[t] = e;
    }
}

__global__ void k_scatter() {
    int i = blockIdx.x * blockDim.x + threadIdx.x;
    if (i >= NT * 2) return;
    int e = g_tokE[i];
    int p = atomicAdd(&g_cursor[e], 1);
    g_rowToken[p]  = i >> 1;
    g_rowWeight[p] = g_tokS[i];
}

// -------------------- pipelined fp16 grouped GEMM ---------------------------
// CTA 128x128, 128 threads (4 warps 2x2, warp tile 64x64), BK=64 (128B rows),
// 3-stage cp.async, ldmatrix fragments, m16n8k16 f16 mma, 2 CTAs/SM.
template<int PHASE>
__global__ void __launch_bounds__(128, 2)
k_gemm(const float* __restrict__ Bias, float* __restrict__ Out) {
    extern __shared__ char smem[];
    int e = g_tileExpert[blockIdx.y];
    if (e < 0) return;
    const int rowBase = blockIdx.y * 128, colBase = blockIdx.x * 128;
    const int tid = threadIdx.x, lane = tid & 31, wid = tid >> 5;

    float* sBias = (float*)smem;
    sBias[tid] = Bias[e * DM + colBase + tid];

    const uint32_t sb = smem_u32(smem) + 1024;

    // ---- producer: 8 A-chunks + 8 B-chunks (16B) per thread per stage ----
    const int tr = tid >> 3, ch = tid & 7;                 // tr 0..15, ch 0..7
    const uint32_t dOff0 = tr * 128 + ((ch * 16) ^ ((tr & 7) << 4));
    const char* wT = (const char*)((PHASE == 1 ? g_w1t : g_w2t) + ((size_t)e << 20));
    const char* aBase = (PHASE == 1) ? (const char*)g_xh
                                     : (const char*)(g_hh + (size_t)rowBase * DM);
    uint32_t aOff[8], aSz[8], bOff[8];
#pragma unroll
    for (int i = 0; i < 8; i++) {
        int row = tr + 16 * i;
        if (PHASE == 1) {
            int tok = g_rowToken[rowBase + row];
            aOff[i] = (uint32_t)(tok < 0 ? 0 : tok) * 2048u + ch * 16;
            aSz[i]  = (tok < 0) ? 0u : 16u;
        } else {
            aOff[i] = (uint32_t)row * 2048u + ch * 16;
            aSz[i]  = 16u;
        }
        bOff[i] = (uint32_t)(colBase + row) * 2048u + ch * 16;
    }

#define PRODUCE(STAGE, KB)                                                      \
    {                                                                           \
        uint32_t base_ = sb + (STAGE) * STG;                                    \
        _Pragma("unroll")                                                       \
        for (int i_ = 0; i_ < 8; i_++) {                                        \
            cp16(base_ + dOff0 + i_ * 2048,         aBase + aOff[i_] + (KB), aSz[i_]); \
            cp16(base_ + 16384 + dOff0 + i_ * 2048, wT + bOff[i_] + (KB), 16); \
        }                                                                       \
    }

    PRODUCE(0, 0);    cp_commit();
    PRODUCE(1, 128);  cp_commit();

    // ---- consumer: ldmatrix addressing ----
    const int g = lane >> 2, tig = lane & 3;
    const int warpM = wid >> 1, warpN = wid & 1;
    const int lm = lane >> 3, lj = lane & 7;       // matrix idx, row within matrix
    const uint32_t swzMask = (uint32_t)lj << 4;
    const uint32_t aHalf = (uint32_t)(lm >> 1) << 4;   // A: m0,m1 khalf0; m2,m3 khalf1
    const uint32_t bHalf = (uint32_t)(lm & 1) << 4;    // B: m0,m2 khalf0; m1,m3 khalf1
    uint32_t aRow[4], bRow[4];
#pragma unroll
    for (int ma = 0; ma < 4; ma++)
        aRow[ma] = (uint32_t)(warpM * 64 + ma * 16 + (lm & 1) * 8 + lj) * 128;
#pragma unroll
    for (int p = 0; p < 4; p++)
        bRow[p] = 16384u + (uint32_t)(warpN * 64 + p * 16 + (lm >> 1) * 8 + lj) * 128;

    float c[4][8][4];
#pragma unroll
    for (int i = 0; i < 4; i++)
#pragma unroll
        for (int j = 0; j < 8; j++)
#pragma unroll
            for (int q = 0; q < 4; q++) c[i][j][q] = 0.f;

    for (int kk = 0; kk < 16; kk++) {       // 16 x BK=64
        cp_wait1();
        __syncthreads();
        if (kk + 2 < 16) {
            int s = (kk + 2) % NSTAGE;
            int kB = (kk + 2) * 128;
            PRODUCE(s, kB);
        }
        cp_commit();   // empty group in tail keeps wait_group<1> counting uniform

        const uint32_t stgA = sb + (kk % NSTAGE) * STG;
#pragma unroll
        for (int k16 = 0; k16 < 4; k16++) {
            const uint32_t kterm = (uint32_t)k16 * 32;   // 16 fp16 = 32B per step
            uint32_t a[4][4], b[4][4];
#pragma unroll
            for (int ma = 0; ma < 4; ma++)
                ldsm4(a[ma], stgA + aRow[ma] + ((kterm + aHalf) ^ swzMask));
#pragma unroll
            for (int p = 0; p < 4; p++)
                ldsm4(b[p], stgA + bRow[p] + ((kterm + bHalf) ^ swzMask));
#pragma unroll
            for (int ma = 0; ma < 4; ma++)
#pragma unroll
                for (int nb = 0; nb < 8; nb++)
                    mma16(c[ma][nb], a[ma],
                          b[nb >> 1][(nb & 1) * 2], b[nb >> 1][(nb & 1) * 2 + 1]);
        }
    }
#undef PRODUCE

    // ---- epilogue ----
#pragma unroll
    for (int ma = 0; ma < 4; ma++) {
#pragma unroll
        for (int half = 0; half < 2; half++) {
            int grow = rowBase + warpM * 64 + ma * 16 + g + half * 8;
            if (PHASE == 1) {
                __half* hrow = g_hh + (size_t)grow * DM + colBase;
#pragma unroll
                for (int nb = 0; nb < 8; nb++) {
                    int cn = warpN * 64 + nb * 8 + tig * 2;
                    float v0 = c[ma][nb][half*2+0] + sBias[cn];
                    float v1 = c[ma][nb][half*2+1] + sBias[cn+1];
                    v0 = fmaxf(v0, 0.f); v1 = fmaxf(v1, 0.f);
                    *(uint32_t*)(hrow + cn) = f2h2(v0, v1);
                }
            } else {
                int tok = g_rowToken[grow];
                if (tok >= 0) {
                    float w = g_rowWeight[grow];
                    float* orow = Out + (size_t)tok * DM + colBase;
#pragma unroll
                    for (int nb = 0; nb < 8; nb++) {
                        int cn = warpN * 64 + nb * 8 + tig * 2;
                        float v0 = (c[ma][nb][half*2+0] + sBias[cn])   * w;
                        float v1 = (c[ma][nb][half*2+1] + sBias[cn+1]) * w;
                        asm volatile("red.global.add.v2.f32 [%0], {%1,%2};"
                                     :: "l"(orow + cn), "f"(v0), "f"(v1) : "memory");
                    }
                }
            }
        }
    }
}

// -------------------- launch -----------------------------------------------
extern "C" void kernel_launch(void* const* d_in, const int* in_sizes, int n_in,
                              void* d_out, int out_size) {
    const float* x  = (const float*)d_in[0];
    const float* gw = (const float*)d_in[1];
    const float* gb = (const float*)d_in[2];
    const float* w1 = (const float*)d_in[3];
    const float* b1 = (const float*)d_in[4];
    const float* w2 = (const float*)d_in[5];
    const float* b2 = (const float*)d_in[6];
    float* out = (float*)d_out;

    static int smemSet = 0;
    if (!smemSet) {
        cudaFuncSetAttribute(k_gemm<1>, cudaFuncAttributeMaxDynamicSharedMemorySize, SMEM_TOTAL);
        cudaFuncSetAttribute(k_gemm<2>, cudaFuncAttributeMaxDynamicSharedMemorySize, SMEM_TOTAL);
        smemSet = 1;
    }

    k_prep<<<dim3(16, 16, 24), 256>>>(w1, w2, out);
    k_gate<<<NT / 64, 256>>>(x, gw, gb);
    k_prefix<<<1, 128>>>();
    k_scatter<<<NT * 2 / 256, 256>>>();
    dim3 gg(DM / 128, MAX_TILES);
    k_gemm<1><<<gg, 128, SMEM_TOTAL>>>(b1, nullptr);
    k_gemm<2><<<gg, 128, SMEM_TOTAL>>>(b2, out);
}

// round 13
// speedup vs baseline: 3.1788x; 1.0121x over previous
#include <cuda_runtime.h>
#include <cuda_fp16.h>
#include <cstdint>
#include <cstddef>

#define NT        32768                 // tokens = B*T
#define DM        1024
#define NE        8
#define ROWS_MAX  (2*NT + NE*128)       // 66560
#define MAX_TILES (ROWS_MAX/128)        // 520
#define STG       32768                 // per-stage: A 16KB + B 16KB (fp16, BK=64)
#define NSTAGE    3
#define SMEM_TOTAL (1024 + NSTAGE*STG)  // ~97 KB -> 2 CTAs/SM

// -------------------- device scratch (static, no allocs) --------------------
__device__ int      g_count[NE];
__device__ int      g_cursor[NE];
__device__ int      g_base[NE+1];
__device__ int      g_tileExpert[MAX_TILES];
__device__ int      g_rowToken[ROWS_MAX];
__device__ float    g_rowWeight[ROWS_MAX];
__device__ int      g_tokE[NT*2];
__device__ float    g_tokS[NT*2];
__device__ __half   g_xh[(size_t)NT * DM];         // x in fp16
__device__ __half   g_hh[(size_t)ROWS_MAX * DM];   // h in fp16
__device__ __half   g_w1t[(size_t)NE * DM * DM];   // w1^T fp16 [e][n][k]
__device__ __half   g_w2t[(size_t)NE * DM * DM];   // w2^T fp16 [e][n][k]

// -------------------- helpers ----------------------------------------------
__device__ __forceinline__ uint32_t smem_u32(const void* p) {
    uint32_t a;
    asm("{ .reg .u64 t; cvta.to.shared.u64 t, %1; cvt.u32.u64 %0, t; }" : "=r"(a) : "l"(p));
    return a;
}
__device__ __forceinline__ uint32_t f2h2(float lo, float hi) {
    uint32_t r;
    asm("cvt.rn.f16x2.f32 %0, %1, %2;" : "=r"(r) : "f"(hi), "f"(lo));
    return r;
}
__device__ __forceinline__ void cp16(uint32_t dst, const void* src, uint32_t sz) {
    asm volatile("cp.async.cg.shared.global [%0], [%1], 16, %2;"
                 :: "r"(dst), "l"(src), "r"(sz) : "memory");
}
__device__ __forceinline__ void cp_commit() { asm volatile("cp.async.commit_group;" ::: "memory"); }
__device__ __forceinline__ void cp_wait1()  { asm volatile("cp.async.wait_group 1;"  ::: "memory"); }
__device__ __forceinline__ void ldsm4(uint32_t* r, uint32_t addr) {
    asm volatile("ldmatrix.sync.aligned.m8n8.x4.shared.b16 {%0,%1,%2,%3}, [%4];"
                 : "=r"(r[0]), "=r"(r[1]), "=r"(r[2]), "=r"(r[3]) : "r"(addr));
}
__device__ __forceinline__ void mma16(float* c, const uint32_t* a, uint32_t b0, uint32_t b1) {
    asm volatile("mma.sync.aligned.m16n8k16.row.col.f32.f16.f16.f32 "
                 "{%0,%1,%2,%3}, {%4,%5,%6,%7}, {%8,%9}, {%0,%1,%2,%3};"
                 : "+f"(c[0]), "+f"(c[1]), "+f"(c[2]), "+f"(c[3])
                 : "r"(a[0]), "r"(a[1]), "r"(a[2]), "r"(a[3]),
                   "r"(b0), "r"(b1));
}

// -------------------- fused prep: transpose (z<16) + init (z>=16) -----------
__global__ void __launch_bounds__(256)
k_prep(const float* __restrict__ W1, const float* __restrict__ W2,
       float* __restrict__ out) {
    if (blockIdx.z < 16) {
        __shared__ __half s[64][68];
        int which = blockIdx.z >> 3;
        int e = blockIdx.z & 7;
        const float* w = (which ? W2 : W1) + (size_t)e * DM * DM;
        __half* wt = (which ? g_w2t : g_w1t) + (size_t)e * DM * DM;
        int k0 = blockIdx.x * 64, n0 = blockIdx.y * 64;
        int c4 = threadIdx.x & 15;
        int r  = threadIdx.x >> 4;
#pragma unroll
        for (int i = 0; i < 4; i++) {
            int kr = r + 16 * i;
            float4 v = *(const float4*)(w + (size_t)(k0 + kr) * DM + n0 + c4 * 4);
            s[c4 * 4 + 0][kr] = __float2half_rn(v.x);
            s[c4 * 4 + 1][kr] = __float2half_rn(v.y);
            s[c4 * 4 + 2][kr] = __float2half_rn(v.z);
            s[c4 * 4 + 3][kr] = __float2half_rn(v.w);
        }
        __syncthreads();
#pragma unroll
        for (int i = 0; i < 4; i++) {
            int nr = r + 16 * i;
            *(uint2*)(wt + (size_t)(n0 + nr) * DM + k0 + c4 * 4) =
                *(const uint2*)&s[nr][c4 * 4];
        }
    } else {
        int slice = blockIdx.z - 16;                      // 0..7
        int cta = blockIdx.y * 16 + blockIdx.x;           // 0..255
        int gid = (slice * 256 + cta) * 256 + threadIdx.x;
        const int nth = 8 * 256 * 256;                    // 524288
        if (gid < NE) g_count[gid] = 0;
        for (int j = gid; j < ROWS_MAX; j += nth) { g_rowToken[j] = -1; g_rowWeight[j] = 0.f; }
        float4 z4 = make_float4(0.f, 0.f, 0.f, 0.f);
        float4* o4 = (float4*)out;
        int n4 = NT * DM / 4;
        for (int j = gid; j < n4; j += nth) o4[j] = z4;
    }
}

// -------------------- gating: 8 tokens per warp, gw staged in smem ----------
#define GTOK 8
__global__ void __launch_bounds__(256)
k_gate(const float* __restrict__ x,
       const float* __restrict__ gw,
       const float* __restrict__ gb) {
    __shared__ float sgw[NE * DM];
    int tid = threadIdx.x;
    for (int i = tid; i < DM * NE / 4; i += 256) {
        float4 v = ((const float4*)gw)[i];
        int k = i >> 1, e0 = (i & 1) * 4;
        sgw[(e0+0) * DM + k] = v.x;
        sgw[(e0+1) * DM + k] = v.y;
        sgw[(e0+2) * DM + k] = v.z;
        sgw[(e0+3) * DM + k] = v.w;
    }
    __syncthreads();

    int warp = tid >> 5, lane = tid & 31;
    int tokBase = (blockIdx.x * 8 + warp) * GTOK;
    const float4* xb = (const float4*)(x + (size_t)tokBase * DM);
    uint2* hb = (uint2*)(g_xh + (size_t)tokBase * DM);

    float acc[GTOK][NE];
#pragma unroll
    for (int t = 0; t < GTOK; t++)
#pragma unroll
        for (int e = 0; e < NE; e++) acc[t][e] = 0.f;

#pragma unroll 1
    for (int k4 = lane; k4 < DM / 4; k4 += 32) {
        float4 xv[GTOK];
#pragma unroll
        for (int t = 0; t < GTOK; t++) {
            xv[t] = xb[t * (DM/4) + k4];
            uint2 u;
            u.x = f2h2(xv[t].x, xv[t].y);
            u.y = f2h2(xv[t].z, xv[t].w);
            hb[t * (DM/4) + k4] = u;
        }
#pragma unroll
        for (int e = 0; e < NE; e++) {
            float4 g4 = ((const float4*)(sgw + e * DM))[k4];
#pragma unroll
            for (int t = 0; t < GTOK; t++)
                acc[t][e] += xv[t].x * g4.x + xv[t].y * g4.y
                           + xv[t].z * g4.z + xv[t].w * g4.w;
        }
    }
#pragma unroll
    for (int off = 16; off; off >>= 1)
#pragma unroll
        for (int t = 0; t < GTOK; t++)
#pragma unroll
            for (int e = 0; e < NE; e++)
                acc[t][e] += __shfl_xor_sync(0xffffffffu, acc[t][e], off);

    if (lane < GTOK) {
        int tok = tokBase + lane;
        float a[NE];
#pragma unroll
        for (int e = 0; e < NE; e++) a[e] = acc[lane][e] + gb[e];
        int e0 = 0; float s0 = a[0];
#pragma unroll
        for (int e = 1; e < NE; e++) if (a[e] > s0) { s0 = a[e]; e0 = e; }
        int e1 = -1; float s1 = -3.4e38f;
#pragma unroll
        for (int e = 0; e < NE; e++) if (e != e0 && a[e] > s1) { s1 = a[e]; e1 = e; }
        g_tokE[2*tok]   = e0;  g_tokS[2*tok]   = s0;
        g_tokE[2*tok+1] = e1;  g_tokS[2*tok+1] = s1;
        atomicAdd(&g_count[e0], 1);
        atomicAdd(&g_count[e1], 1);
    }
}

// -------------------- prefix (128-aligned) + tile->expert -------------------
__global__ void k_prefix() {
    __shared__ int base[NE+1];
    if (threadIdx.x == 0) {
        int b = 0; base[0] = 0; g_base[0] = 0;
        for (int e = 0; e < NE; e++) {
            g_cursor[e] = b;
            b += ((g_count[e] + 127) >> 7) << 7;
            base[e+1] = b; g_base[e+1] = b;
        }
    }
    __syncthreads();
    for (int t = threadIdx.x; t < MAX_TILES; t += blockDim.x) {
        int r = t << 7;
        int e = -1;
#pragma unroll
        for (int q = 0; q < NE; q++)
            if (r >= base[q] && r < base[q+1]) e = q;
        g_tileExpert[t] = e;
    }
}

// -------------------- scatter: CTA-aggregated atomics ------------------------
// smem histogram -> ONE global atomic per expert per CTA (2048 total vs 65536).
__global__ void __launch_bounds__(256)
k_scatter() {
    __shared__ int hist[NE];
    __shared__ int base[NE];
    int tid = threadIdx.x;
    if (tid < NE) hist[tid] = 0;
    __syncthreads();
    int i = blockIdx.x * 256 + tid;          // grid exactly covers NT*2
    int e = g_tokE[i];
    int local = atomicAdd(&hist[e], 1);
    __syncthreads();
    if (tid < NE) base[tid] = atomicAdd(&g_cursor[tid], hist[tid]);
    __syncthreads();
    int p = base[e] + local;
    g_rowToken[p]  = i >> 1;
    g_rowWeight[p] = g_tokS[i];
}

// -------------------- pipelined fp16 grouped GEMM ---------------------------
// CTA 128x128, 128 threads (4 warps 2x2, warp tile 64x64), BK=64 (128B rows),
// 3-stage cp.async, ldmatrix fragments, m16n8k16 f16 mma, 2 CTAs/SM.
template<int PHASE>
__global__ void __launch_bounds__(128, 2)
k_gemm(const float* __restrict__ Bias, float* __restrict__ Out) {
    extern __shared__ char smem[];
    int e = g_tileExpert[blockIdx.y];
    if (e < 0) return;
    const int rowBase = blockIdx.y * 128, colBase = blockIdx.x * 128;
    const int tid = threadIdx.x, lane = tid & 31, wid = tid >> 5;

    float* sBias = (float*)smem;
    sBias[tid] = Bias[e * DM + colBase + tid];

    const uint32_t sb = smem_u32(smem) + 1024;

    // ---- producer: 8 A-chunks + 8 B-chunks (16B) per thread per stage ----
    const int tr = tid >> 3, ch = tid & 7;                 // tr 0..15, ch 0..7
    const uint32_t dOff0 = tr * 128 + ((ch * 16) ^ ((tr & 7) << 4));
    const char* wT = (const char*)((PHASE == 1 ? g_w1t : g_w2t) + ((size_t)e << 20));
    const char* aBase = (PHASE == 1) ? (const char*)g_xh
                                     : (const char*)(g_hh + (size_t)rowBase * DM);
    uint32_t aOff[8], aSz[8], bOff[8];
#pragma unroll
    for (int i = 0; i < 8; i++) {
        int row = tr + 16 * i;
        if (PHASE == 1) {
            int tok = g_rowToken[rowBase + row];
            aOff[i] = (uint32_t)(tok < 0 ? 0 : tok) * 2048u + ch * 16;
            aSz[i]  = (tok < 0) ? 0u : 16u;
        } else {
            aOff[i] = (uint32_t)row * 2048u + ch * 16;
            aSz[i]  = 16u;
        }
        bOff[i] = (uint32_t)(colBase + row) * 2048u + ch * 16;
    }

#define PRODUCE(STAGE, KB)                                                      \
    {                                                                           \
        uint32_t base_ = sb + (STAGE) * STG;                                    \
        _Pragma("unroll")                                                       \
        for (int i_ = 0; i_ < 8; i_++) {                                        \
            cp16(base_ + dOff0 + i_ * 2048,         aBase + aOff[i_] + (KB), aSz[i_]); \
            cp16(base_ + 16384 + dOff0 + i_ * 2048, wT + bOff[i_] + (KB), 16); \
        }                                                                       \
    }

    PRODUCE(0, 0);    cp_commit();
    PRODUCE(1, 128);  cp_commit();

    // ---- consumer: ldmatrix addressing ----
    const int g = lane >> 2, tig = lane & 3;
    const int warpM = wid >> 1, warpN = wid & 1;
    const int lm = lane >> 3, lj = lane & 7;       // matrix idx, row within matrix
    const uint32_t swzMask = (uint32_t)lj << 4;
    const uint32_t aHalf = (uint32_t)(lm >> 1) << 4;   // A: m0,m1 khalf0; m2,m3 khalf1
    const uint32_t bHalf = (uint32_t)(lm & 1) << 4;    // B: m0,m2 khalf0; m1,m3 khalf1
    uint32_t aRow[4], bRow[4];
#pragma unroll
    for (int ma = 0; ma < 4; ma++)
        aRow[ma] = (uint32_t)(warpM * 64 + ma * 16 + (lm & 1) * 8 + lj) * 128;
#pragma unroll
    for (int p = 0; p < 4; p++)
        bRow[p] = 16384u + (uint32_t)(warpN * 64 + p * 16 + (lm >> 1) * 8 + lj) * 128;

    float c[4][8][4];
#pragma unroll
    for (int i = 0; i < 4; i++)
#pragma unroll
        for (int j = 0; j < 8; j++)
#pragma unroll
            for (int q = 0; q < 4; q++) c[i][j][q] = 0.f;

    for (int kk = 0; kk < 16; kk++) {       // 16 x BK=64
        cp_wait1();
        __syncthreads();
        if (kk + 2 < 16) {
            int s = (kk + 2) % NSTAGE;
            int kB = (kk + 2) * 128;
            PRODUCE(s, kB);
        }
        cp_commit();   // empty group in tail keeps wait_group<1> counting uniform

        const uint32_t stgA = sb + (kk % NSTAGE) * STG;
#pragma unroll
        for (int k16 = 0; k16 < 4; k16++) {
            const uint32_t kterm = (uint32_t)k16 * 32;   // 16 fp16 = 32B per step
            uint32_t a[4][4], b[4][4];
#pragma unroll
            for (int ma = 0; ma < 4; ma++)
                ldsm4(a[ma], stgA + aRow[ma] + ((kterm + aHalf) ^ swzMask));
#pragma unroll
            for (int p = 0; p < 4; p++)
                ldsm4(b[p], stgA + bRow[p] + ((kterm + bHalf) ^ swzMask));
#pragma unroll
            for (int ma = 0; ma < 4; ma++)
#pragma unroll
                for (int nb = 0; nb < 8; nb++)
                    mma16(c[ma][nb], a[ma],
                          b[nb >> 1][(nb & 1) * 2], b[nb >> 1][(nb & 1) * 2 + 1]);
        }
    }
#undef PRODUCE

    // ---- epilogue ----
#pragma unroll
    for (int ma = 0; ma < 4; ma++) {
#pragma unroll
        for (int half = 0; half < 2; half++) {
            int grow = rowBase + warpM * 64 + ma * 16 + g + half * 8;
            if (PHASE == 1) {
                __half* hrow = g_hh + (size_t)grow * DM + colBase;
#pragma unroll
                for (int nb = 0; nb < 8; nb++) {
                    int cn = warpN * 64 + nb * 8 + tig * 2;
                    float v0 = c[ma][nb][half*2+0] + sBias[cn];
                    float v1 = c[ma][nb][half*2+1] + sBias[cn+1];
                    v0 = fmaxf(v0, 0.f); v1 = fmaxf(v1, 0.f);
                    *(uint32_t*)(hrow + cn) = f2h2(v0, v1);
                }
            } else {
                int tok = g_rowToken[grow];
                if (tok >= 0) {
                    float w = g_rowWeight[grow];
                    float* orow = Out + (size_t)tok * DM + colBase;
#pragma unroll
                    for (int nb = 0; nb < 8; nb++) {
                        int cn = warpN * 64 + nb * 8 + tig * 2;
                        float v0 = (c[ma][nb][half*2+0] + sBias[cn])   * w;
                        float v1 = (c[ma][nb][half*2+1] + sBias[cn+1]) * w;
                        asm volatile("red.global.add.v2.f32 [%0], {%1,%2};"
                                     :: "l"(orow + cn), "f"(v0), "f"(v1) : "memory");
                    }
                }
            }
        }
    }
}

// -------------------- launch -----------------------------------------------
extern "C" void kernel_launch(void* const* d_in, const int* in_sizes, int n_in,
                              void* d_out, int out_size) {
    const float* x  = (const float*)d_in[0];
    const float* gw = (const float*)d_in[1];
    const float* gb = (const float*)d_in[2];
    const float* w1 = (const float*)d_in[3];
    const float* b1 = (const float*)d_in[4];
    const float* w2 = (const float*)d_in[5];
    const float* b2 = (const float*)d_in[6];
    float* out = (float*)d_out;

    static int smemSet = 0;
    if (!smemSet) {
        cudaFuncSetAttribute(k_gemm<1>, cudaFuncAttributeMaxDynamicSharedMemorySize, SMEM_TOTAL);
        cudaFuncSetAttribute(k_gemm<2>, cudaFuncAttributeMaxDynamicSharedMemorySize, SMEM_TOTAL);
        smemSet = 1;
    }

    k_prep<<<dim3(16, 16, 24), 256>>>(w1, w2, out);
    k_gate<<<NT / 64, 256>>>(x, gw, gb);
    k_prefix<<<1, 128>>>();
    k_scatter<<<NT * 2 / 256, 256>>>();
    dim3 gg(DM / 128, MAX_TILES);
    k_gemm<1><<<gg, 128, SMEM_TOTAL>>>(b1, nullptr);
    k_gemm<2><<<gg, 128, SMEM_TOTAL>>>(b2, out);
}